// round 12
// baseline (speedup 1.0000x reference)
#include <cuda_runtime.h>
#include <cuda_fp16.h>
#include <math.h>

#define N_NODES  50000
#define F_IN     256
#define HEADS    3
#define OUT_C    128
#define HO       384      // HEADS*OUT_C
#define NG       64
#define NC       2
#define E_MAX    800000
#define SLOPE    0.2f

// ---------------- scratch (device globals; zero-initialized at load) ---------
__device__ __half g_x16[N_NODES * F_IN];     // fp16 x     (25.6 MB)
__device__ __half g_w16[F_IN * HO];          // fp16 W
__device__ __half g_h16[N_NODES * HO];       // fp16 x@W   (38.4 MB)
__device__ float g_a4_src[N_NODES * 4];      // padded [node][4] logits
__device__ float g_a4_dst[N_NODES * 4];
__device__ int   g_deg[N_NODES];             // zeroed by k_agg each call
__device__ int   g_roff[N_NODES + 1];        // exclusive offsets, roff[n]=E
__device__ int   g_cursor[N_NODES];
__device__ int   g_csr[E_MAX];
__device__ float4 g_pex[E_MAX];              // per-edge exps at CSR position
__device__ float g_den4[N_NODES * 4];        // denominators (zeroed by k_pre)
__device__ float g_out2[NG * NC];            // zeroed by k_final each call
__device__ float g_cnt[NG];                  // zeroed by k_final each call

// ---------------- helpers ----------------
__device__ __forceinline__ unsigned sptr(const void* p) {
    return (unsigned)__cvta_generic_to_shared(p);
}

__device__ __forceinline__ void cp_async16(unsigned dst, const void* src, bool pred) {
    int sz = pred ? 16 : 0;
    asm volatile("cp.async.cg.shared.global [%0], [%1], 16, %2;"
                 :: "r"(dst), "l"(src), "r"(sz));
}
#define CP_COMMIT() asm volatile("cp.async.commit_group;")
#define CP_WAIT1()  asm volatile("cp.async.wait_group 1;")
#define CP_WAIT0()  asm volatile("cp.async.wait_group 0;")

__device__ __forceinline__ void red_add_v4(float* addr, float a, float b,
                                           float c, float d) {
    asm volatile("red.global.add.v4.f32 [%0], {%1,%2,%3,%4};"
                 :: "l"(addr), "f"(a), "f"(b), "f"(c), "f"(d) : "memory");
}

#define LDSM4(r0, r1, r2, r3, addr) \
    asm volatile("ldmatrix.sync.aligned.m8n8.x4.shared.b16 {%0,%1,%2,%3},[%4];" \
                 : "=r"(r0), "=r"(r1), "=r"(r2), "=r"(r3) : "r"(addr))

#define LDSM4T(r0, r1, r2, r3, addr) \
    asm volatile("ldmatrix.sync.aligned.m8n8.x4.trans.shared.b16 {%0,%1,%2,%3},[%4];" \
                 : "=r"(r0), "=r"(r1), "=r"(r2), "=r"(r3) : "r"(addr))

#define MMA16816(c, a0, a1, a2, a3, b0, b1) \
    asm volatile("mma.sync.aligned.m16n8k16.row.col.f32.f16.f16.f32 " \
                 "{%0,%1,%2,%3},{%4,%5,%6,%7},{%8,%9},{%0,%1,%2,%3};" \
                 : "+f"((c)[0]), "+f"((c)[1]), "+f"((c)[2]), "+f"((c)[3]) \
                 : "r"(a0), "r"(a1), "r"(a2), "r"(a3), "r"(b0), "r"(b1))

// ---------------- K1: hist (blocks [0,histB)) || cvt + den4 zero (rest) ------
__global__ void __launch_bounds__(256) k_pre(const float* __restrict__ x,
                                             const float* __restrict__ W,
                                             const int* __restrict__ ei,
                                             int E, int n, int histB) {
    if ((int)blockIdx.x < histB) {
        int i = (blockIdx.x * blockDim.x + threadIdx.x) * 4;
        if (i + 3 < E) {
            int4 d = *(const int4*)&ei[E + i];
            atomicAdd(&g_deg[d.x], 1);
            atomicAdd(&g_deg[d.y], 1);
            atomicAdd(&g_deg[d.z], 1);
            atomicAdd(&g_deg[d.w], 1);
        } else {
            for (int k = 0; k < 4 && i + k < E; k++)
                atomicAdd(&g_deg[ei[E + i + k]], 1);
        }
        return;
    }
    int i = (blockIdx.x - histB) * blockDim.x + threadIdx.x;
    int totalx = (n * F_IN) >> 3;
    if (i < totalx) {
        const float4* p = (const float4*)x + i * 2;
        float4 v0 = p[0], v1 = p[1];
        __half2 h0 = __floats2half2_rn(v0.x, v0.y);
        __half2 h1 = __floats2half2_rn(v0.z, v0.w);
        __half2 h2 = __floats2half2_rn(v1.x, v1.y);
        __half2 h3 = __floats2half2_rn(v1.z, v1.w);
        uint4 u;
        u.x = *(unsigned*)&h0; u.y = *(unsigned*)&h1;
        u.z = *(unsigned*)&h2; u.w = *(unsigned*)&h3;
        *(uint4*)&g_x16[i * 8] = u;
    }
    int totalw = (F_IN * HO) >> 3;   // 12288
    if (i < totalw) {
        const float4* p = (const float4*)W + i * 2;
        float4 v0 = p[0], v1 = p[1];
        __half2 h0 = __floats2half2_rn(v0.x, v0.y);
        __half2 h1 = __floats2half2_rn(v0.z, v0.w);
        __half2 h2 = __floats2half2_rn(v1.x, v1.y);
        __half2 h3 = __floats2half2_rn(v1.z, v1.w);
        uint4 u;
        u.x = *(unsigned*)&h0; u.y = *(unsigned*)&h1;
        u.z = *(unsigned*)&h2; u.w = *(unsigned*)&h3;
        *(uint4*)&g_w16[i * 8] = u;
    }
    if (i < n)
        *(float4*)&g_den4[i * 4] = make_float4(0.f, 0.f, 0.f, 0.f);
}

// ---------------- K2: GEMM (blocks >= 1) || block-serial scan (block 0) ------
__global__ void __launch_bounds__(256) k_gemm(const float* __restrict__ att_src,
                                              const float* __restrict__ att_dst,
                                              int n) {
    __shared__ __half Ah[2][128 * 40];
    __shared__ __half Bh[2][32 * 136];
    __shared__ float Ps[128][4];
    __shared__ float Pd[128][4];
    __shared__ int wsum[8];
    __shared__ int s_carry;

    const int t = threadIdx.x;

    if (blockIdx.x == 0) {
        int lane = t & 31, w = t >> 5;
        if (t == 0) s_carry = 0;
        __syncthreads();
        for (int base = 0; base < n; base += 1024) {
            int i = base + t * 4;
            int4 v = make_int4(0, 0, 0, 0);
            if (i + 3 < n) v = *(const int4*)&g_deg[i];
            else if (i < n) {
                v.x = g_deg[i];
                if (i + 1 < n) v.y = g_deg[i + 1];
                if (i + 2 < n) v.z = g_deg[i + 2];
            }
            int s0 = v.x, s1 = s0 + v.y, s2 = s1 + v.z, s3 = s2 + v.w;
            int tot = s3;
#pragma unroll
            for (int o = 1; o < 32; o <<= 1) {
                int u = __shfl_up_sync(0xFFFFFFFFu, tot, o);
                if (lane >= o) tot += u;
            }
            if (lane == 31) wsum[w] = tot;
            __syncthreads();
            if (t < 8) {
                int ws = wsum[t];
#pragma unroll
                for (int o = 1; o < 8; o <<= 1) {
                    int u = __shfl_up_sync(0x000000FFu, ws, o);
                    if (t >= o) ws += u;
                }
                wsum[t] = ws;
            }
            __syncthreads();
            int carry = s_carry;
            int off = carry + (w > 0 ? wsum[w - 1] : 0) + (tot - s3);
            if (i < n) {
                if (i + 3 < n) {
                    int4 r = make_int4(off, off + s0, off + s1, off + s2);
                    *(int4*)&g_roff[i] = r;
                    *(int4*)&g_cursor[i] = r;
                } else {
                    g_roff[i] = off;          g_cursor[i] = off;
                    if (i + 1 < n) { g_roff[i+1] = off + s0; g_cursor[i+1] = off + s0; }
                    if (i + 2 < n) { g_roff[i+2] = off + s1; g_cursor[i+2] = off + s1; }
                }
            }
            __syncthreads();
            if (t == 255) s_carry = carry + wsum[7];
            __syncthreads();
        }
        if (t == 0) g_roff[n] = s_carry;   // total edge count
        return;
    }

    const int idx = blockIdx.x - 1;
    const int head = idx % HEADS;
    const int row0 = (idx / HEADS) * 128;
    const int lane = t & 31;
    const int wid = t >> 5;
    const int warp_m = wid & 1;
    const int warp_n = wid >> 1;

    float acc[4][4][4];
#pragma unroll
    for (int mf = 0; mf < 4; mf++)
#pragma unroll
        for (int nf = 0; nf < 4; nf++)
#pragma unroll
            for (int r = 0; r < 4; r++) acc[mf][nf][r] = 0.0f;

    auto issue = [&](int st, int kk) {
#pragma unroll
        for (int l = 0; l < 2; l++) {
            int q = t + l * 256;
            int row = q >> 2, seg = q & 3;
            bool pred = (row0 + row) < n;
            const __half* src = &g_x16[(long)(row0 + row) * F_IN + kk + seg * 8];
            cp_async16(sptr(&Ah[st][row * 40 + seg * 8]), src, pred);
        }
#pragma unroll
        for (int l = 0; l < 2; l++) {
            int q = t + l * 256;
            int kr = q >> 4, seg = q & 15;
            const __half* src = &g_w16[(long)(kk + kr) * HO + head * 128 + seg * 8];
            cp_async16(sptr(&Bh[st][kr * 136 + seg * 8]), src, true);
        }
        CP_COMMIT();
    };

    issue(0, 0);

    const int NIT = F_IN / 32;   // 8
    for (int i = 0; i < NIT; i++) {
        int st = i & 1;
        if (i + 1 < NIT) { issue((i + 1) & 1, (i + 1) * 32); CP_WAIT1(); }
        else             { CP_WAIT0(); }
        __syncthreads();

#pragma unroll
        for (int s = 0; s < 2; s++) {
            unsigned a[4][4];
#pragma unroll
            for (int mf = 0; mf < 4; mf++) {
                unsigned addr = sptr(&Ah[st][(warp_m * 64 + mf * 16 + (lane & 15)) * 40 +
                                            s * 16 + (lane >> 4) * 8]);
                LDSM4(a[mf][0], a[mf][1], a[mf][2], a[mf][3], addr);
            }
            unsigned b[2][4];
#pragma unroll
            for (int nf2 = 0; nf2 < 2; nf2++) {
                unsigned addr = sptr(&Bh[st][(s * 16 + (lane & 15)) * 136 +
                                            warp_n * 32 + nf2 * 16 + ((lane & 16) ? 8 : 0)]);
                LDSM4T(b[nf2][0], b[nf2][1], b[nf2][2], b[nf2][3], addr);
            }
#pragma unroll
            for (int mf = 0; mf < 4; mf++)
#pragma unroll
                for (int nf = 0; nf < 4; nf++) {
                    int nf2 = nf >> 1;
                    int bo = (nf & 1) * 2;
                    MMA16816(acc[mf][nf], a[mf][0], a[mf][1], a[mf][2], a[mf][3],
                             b[nf2][bo], b[nf2][bo + 1]);
                }
        }
        __syncthreads();
    }

    float avs[4][2], avd[4][2];
#pragma unroll
    for (int nf = 0; nf < 4; nf++)
#pragma unroll
        for (int j = 0; j < 2; j++) {
            int c = head * 128 + warp_n * 32 + nf * 8 + (lane & 3) * 2 + j;
            avs[nf][j] = att_src[c];
            avd[nf][j] = att_dst[c];
        }

#pragma unroll
    for (int mf = 0; mf < 4; mf++)
#pragma unroll
        for (int rh = 0; rh < 2; rh++) {
            float ps = 0.0f, pd = 0.0f;
#pragma unroll
            for (int nf = 0; nf < 4; nf++)
#pragma unroll
                for (int j = 0; j < 2; j++) {
                    float v = acc[mf][nf][rh * 2 + j];
                    ps = fmaf(v, avs[nf][j], ps);
                    pd = fmaf(v, avd[nf][j], pd);
                }
            ps += __shfl_xor_sync(0xFFFFFFFFu, ps, 1);
            ps += __shfl_xor_sync(0xFFFFFFFFu, ps, 2);
            pd += __shfl_xor_sync(0xFFFFFFFFu, pd, 1);
            pd += __shfl_xor_sync(0xFFFFFFFFu, pd, 2);
            int rloc = warp_m * 64 + mf * 16 + (lane >> 2) + rh * 8;
            if ((lane & 3) == 0) { Ps[rloc][warp_n] = ps; Pd[rloc][warp_n] = pd; }
            int grow = row0 + rloc;
            if (grow < n) {
#pragma unroll
                for (int nf = 0; nf < 4; nf++) {
                    __half2 hh = __floats2half2_rn(acc[mf][nf][rh * 2],
                                                   acc[mf][nf][rh * 2 + 1]);
                    *(__half2*)&g_h16[(long)grow * HO + head * 128 + warp_n * 32 +
                                      nf * 8 + (lane & 3) * 2] = hh;
                }
            }
        }
    __syncthreads();

    int r = t & 127;
    int grow = row0 + r;
    if (grow < n) {
        if (t < 128) {
            g_a4_src[grow * 4 + head] = Ps[r][0] + Ps[r][1] + Ps[r][2] + Ps[r][3];
        } else {
            g_a4_dst[grow * 4 + head] = Pd[r][0] + Pd[r][1] + Pd[r][2] + Pd[r][3];
        }
    }
}

// ---------------- K3: CSR fill + edge exps + denominators --------------------
__global__ void k_fill(const int* __restrict__ ei, int E) {
    int i = (blockIdx.x * blockDim.x + threadIdx.x) * 2;
#pragma unroll
    for (int k = 0; k < 2; k++) {
        int e = i + k;
        if (e >= E) return;
        int s = ei[e];
        int d = ei[E + e];
        int pos = atomicAdd(&g_cursor[d], 1);
        g_csr[pos] = s;
        float4 as = *(const float4*)&g_a4_src[s * 4];
        float4 ad = *(const float4*)&g_a4_dst[d * 4];
        float v0 = as.x + ad.x; v0 = v0 > 0.0f ? v0 : SLOPE * v0;
        float v1 = as.y + ad.y; v1 = v1 > 0.0f ? v1 : SLOPE * v1;
        float v2 = as.z + ad.z; v2 = v2 > 0.0f ? v2 : SLOPE * v2;
        float p0 = __expf(v0), p1 = __expf(v1), p2 = __expf(v2);
        g_pex[pos] = make_float4(p0, p1, p2, 0.0f);
        red_add_v4(&g_den4[d * 4], p0, p1, p2, 0.0f);
    }
}

// ---------------- K4: gather-aggregate + relu + FC (warp per node-head) ------
__global__ void __launch_bounds__(256) k_agg(const int* __restrict__ batch,
                                             const float* __restrict__ bias,
                                             const float* __restrict__ fc_w,
                                             int n) {
    int w = (blockIdx.x * blockDim.x + threadIdx.x) >> 5;
    int lane = threadIdx.x & 31;
    if (w >= n * HEADS) return;
    int d = w / HEADS;
    int h = w - d * HEADS;

    const int start = g_roff[d];
    const int cnt = g_roff[d + 1] - start;
    const int col = h * OUT_C + lane * 4;

    // self-loop exp (warp-uniform scalar computation)
    float v = g_a4_src[d * 4 + h] + g_a4_dst[d * 4 + h];
    v = v > 0.0f ? v : SLOPE * v;
    float exl = __expf(v);

    float acc0, acc1, acc2, acc3;
    {
        uint2 u = *(const uint2*)&g_h16[(long)d * HO + col];
        float2 fa = __half22float2(*(__half2*)&u.x);
        float2 fb = __half22float2(*(__half2*)&u.y);
        acc0 = exl * fa.x; acc1 = exl * fa.y;
        acc2 = exl * fb.x; acc3 = exl * fb.y;
    }

    const float* pexf = (const float*)g_pex;
    int j = 0;
    for (; j + 4 <= cnt; j += 4) {
        int s0 = g_csr[start + j];
        int s1 = g_csr[start + j + 1];
        int s2 = g_csr[start + j + 2];
        int s3 = g_csr[start + j + 3];
        float q0 = pexf[(start + j) * 4 + h];
        float q1 = pexf[(start + j + 1) * 4 + h];
        float q2 = pexf[(start + j + 2) * 4 + h];
        float q3 = pexf[(start + j + 3) * 4 + h];
        uint2 u0 = *(const uint2*)&g_h16[(long)s0 * HO + col];
        uint2 u1 = *(const uint2*)&g_h16[(long)s1 * HO + col];
        uint2 u2 = *(const uint2*)&g_h16[(long)s2 * HO + col];
        uint2 u3 = *(const uint2*)&g_h16[(long)s3 * HO + col];
        {
            float2 fa = __half22float2(*(__half2*)&u0.x);
            float2 fb = __half22float2(*(__half2*)&u0.y);
            acc0 = fmaf(q0, fa.x, acc0); acc1 = fmaf(q0, fa.y, acc1);
            acc2 = fmaf(q0, fb.x, acc2); acc3 = fmaf(q0, fb.y, acc3);
        }
        {
            float2 fa = __half22float2(*(__half2*)&u1.x);
            float2 fb = __half22float2(*(__half2*)&u1.y);
            acc0 = fmaf(q1, fa.x, acc0); acc1 = fmaf(q1, fa.y, acc1);
            acc2 = fmaf(q1, fb.x, acc2); acc3 = fmaf(q1, fb.y, acc3);
        }
        {
            float2 fa = __half22float2(*(__half2*)&u2.x);
            float2 fb = __half22float2(*(__half2*)&u2.y);
            acc0 = fmaf(q2, fa.x, acc0); acc1 = fmaf(q2, fa.y, acc1);
            acc2 = fmaf(q2, fb.x, acc2); acc3 = fmaf(q2, fb.y, acc3);
        }
        {
            float2 fa = __half22float2(*(__half2*)&u3.x);
            float2 fb = __half22float2(*(__half2*)&u3.y);
            acc0 = fmaf(q3, fa.x, acc0); acc1 = fmaf(q3, fa.y, acc1);
            acc2 = fmaf(q3, fb.x, acc2); acc3 = fmaf(q3, fb.y, acc3);
        }
    }
    for (; j < cnt; j++) {
        int s0 = g_csr[start + j];
        float q0 = pexf[(start + j) * 4 + h];
        uint2 u0 = *(const uint2*)&g_h16[(long)s0 * HO + col];
        float2 fa = __half22float2(*(__half2*)&u0.x);
        float2 fb = __half22float2(*(__half2*)&u0.y);
        acc0 = fmaf(q0, fa.x, acc0); acc1 = fmaf(q0, fa.y, acc1);
        acc2 = fmaf(q0, fb.x, acc2); acc3 = fmaf(q0, fb.y, acc3);
    }

    float den = g_den4[d * 4 + h] + exl;
    float inv = 1.0f / (den + 1e-16f);

    float4 b = *(const float4*)&bias[col];
    float r0 = fmaxf(acc0 * inv + b.x, 0.0f);
    float r1 = fmaxf(acc1 * inv + b.y, 0.0f);
    float r2 = fmaxf(acc2 * inv + b.z, 0.0f);
    float r3 = fmaxf(acc3 * inv + b.w, 0.0f);

    float2 w0 = *(const float2*)&fc_w[(col + 0) * NC];
    float2 w1 = *(const float2*)&fc_w[(col + 1) * NC];
    float2 w2 = *(const float2*)&fc_w[(col + 2) * NC];
    float2 w3 = *(const float2*)&fc_w[(col + 3) * NC];
    float c0s = r0 * w0.x + r1 * w1.x + r2 * w2.x + r3 * w3.x;
    float c1s = r0 * w0.y + r1 * w1.y + r2 * w2.y + r3 * w3.y;

#pragma unroll
    for (int o = 16; o > 0; o >>= 1) {
        c0s += __shfl_xor_sync(0xFFFFFFFFu, c0s, o);
        c1s += __shfl_xor_sync(0xFFFFFFFFu, c1s, o);
    }
    if (lane == 0) {
        int g = batch[d];
        atomicAdd(&g_out2[g * NC + 0], c0s);
        atomicAdd(&g_out2[g * NC + 1], c1s);
        if (h == 0) {
            atomicAdd(&g_cnt[g], 1.0f);
            g_deg[d] = 0;   // safe: k_agg no longer reads g_deg
        }
    }
}

// ---------------- K5: final mean + bias (+ scratch reset) --------------------
__global__ void k_final(const float* __restrict__ fc_b,
                        float* __restrict__ out) {
    int t = threadIdx.x;   // 128 threads
    float val = 0.0f;
    int g = t >> 1, c = t & 1;
    if (t < NG * NC) {
        float cnt = fmaxf(g_cnt[g], 1.0f);
        val = g_out2[t] / cnt + fc_b[c];
    }
    __syncthreads();
    if (t < NG * NC) {
        out[t] = val;
        g_out2[t] = 0.0f;
    }
    if (t < NG) g_cnt[t] = 0.0f;
}

// ---------------- launch ----------------
extern "C" void kernel_launch(void* const* d_in, const int* in_sizes, int n_in,
                              void* d_out, int out_size) {
    const float* x       = (const float*)d_in[0];
    const int*   ei      = (const int*)  d_in[1];
    const int*   batch   = (const int*)  d_in[2];
    const float* W       = (const float*)d_in[3];
    const float* att_src = (const float*)d_in[4];
    const float* att_dst = (const float*)d_in[5];
    const float* bias    = (const float*)d_in[6];
    const float* fc_w    = (const float*)d_in[7];
    const float* fc_b    = (const float*)d_in[8];
    float* out = (float*)d_out;

    const int n = in_sizes[0] / F_IN;       // 50000
    const int E = in_sizes[1] / 2;          // 800000

    int histB = (E / 4 + 255) / 256;        // 782
    int cvtB  = ((n * F_IN) / 8 + 255) / 256;  // 6250
    k_pre<<<histB + cvtB, 256>>>(x, W, ei, E, n, histB);

    int mt = (n + 127) / 128;               // 391
    k_gemm<<<1 + HEADS * mt, 256>>>(att_src, att_dst, n);

    k_fill<<<(E / 2 + 255) / 256, 256>>>(ei, E);
    k_agg<<<((n * HEADS) * 32 + 255) / 256, 256>>>(batch, bias, fc_w, n);
    k_final<<<1, 128>>>(fc_b, out);
}

// round 13
// speedup vs baseline: 1.9992x; 1.9992x over previous
#include <cuda_runtime.h>
#include <cuda_fp16.h>
#include <math.h>

#define N_NODES  50000
#define F_IN     256
#define HEADS    3
#define OUT_C    128
#define HO       384      // HEADS*OUT_C
#define NG       64
#define NC       2
#define E_MAX    800000
#define SLOPE    0.2f

// ---------------- scratch (device globals; zero-initialized at load) ---------
__device__ __half g_x16[N_NODES * F_IN];     // fp16 x     (25.6 MB)
__device__ __half g_w16[F_IN * HO];          // fp16 W
__device__ __half g_h16[N_NODES * HO];       // fp16 x@W   (38.4 MB)
__device__ float g_a4_src[N_NODES * 4];      // padded [node][4] logits
__device__ float g_a4_dst[N_NODES * 4];
__device__ int   g_deg[N_NODES];             // zeroed by k_agg each call
__device__ int   g_roff[N_NODES + 1];
__device__ int   g_cursor[N_NODES];
__device__ int   g_csr[E_MAX];
__device__ float g_out2[NG * NC];            // zeroed by k_final each call
__device__ float g_cnt[NG];                  // zeroed by k_final each call

// ---------------- helpers ----------------
__device__ __forceinline__ unsigned sptr(const void* p) {
    return (unsigned)__cvta_generic_to_shared(p);
}

__device__ __forceinline__ void cp_async16(unsigned dst, const void* src, bool pred) {
    int sz = pred ? 16 : 0;
    asm volatile("cp.async.cg.shared.global [%0], [%1], 16, %2;"
                 :: "r"(dst), "l"(src), "r"(sz));
}
#define CP_COMMIT() asm volatile("cp.async.commit_group;")
#define CP_WAIT1()  asm volatile("cp.async.wait_group 1;")
#define CP_WAIT0()  asm volatile("cp.async.wait_group 0;")

#define LDSM4(r0, r1, r2, r3, addr) \
    asm volatile("ldmatrix.sync.aligned.m8n8.x4.shared.b16 {%0,%1,%2,%3},[%4];" \
                 : "=r"(r0), "=r"(r1), "=r"(r2), "=r"(r3) : "r"(addr))

#define LDSM4T(r0, r1, r2, r3, addr) \
    asm volatile("ldmatrix.sync.aligned.m8n8.x4.trans.shared.b16 {%0,%1,%2,%3},[%4];" \
                 : "=r"(r0), "=r"(r1), "=r"(r2), "=r"(r3) : "r"(addr))

#define MMA16816(c, a0, a1, a2, a3, b0, b1) \
    asm volatile("mma.sync.aligned.m16n8k16.row.col.f32.f16.f16.f32 " \
                 "{%0,%1,%2,%3},{%4,%5,%6,%7},{%8,%9},{%0,%1,%2,%3};" \
                 : "+f"((c)[0]), "+f"((c)[1]), "+f"((c)[2]), "+f"((c)[3]) \
                 : "r"(a0), "r"(a1), "r"(a2), "r"(a3), "r"(b0), "r"(b1))

// ---------------- K1: hist (blocks [0,histB)) || cvt (rest) ------------------
__global__ void __launch_bounds__(256) k_pre(const float* __restrict__ x,
                                             const float* __restrict__ W,
                                             const int* __restrict__ ei,
                                             int E, int n, int histB) {
    if ((int)blockIdx.x < histB) {
        int i = (blockIdx.x * blockDim.x + threadIdx.x) * 4;
        if (i + 3 < E) {
            int4 d = *(const int4*)&ei[E + i];
            atomicAdd(&g_deg[d.x], 1);
            atomicAdd(&g_deg[d.y], 1);
            atomicAdd(&g_deg[d.z], 1);
            atomicAdd(&g_deg[d.w], 1);
        } else {
            for (int k = 0; k < 4 && i + k < E; k++)
                atomicAdd(&g_deg[ei[E + i + k]], 1);
        }
        return;
    }
    int i = (blockIdx.x - histB) * blockDim.x + threadIdx.x;
    int totalx = (n * F_IN) >> 3;
    if (i < totalx) {
        const float4* p = (const float4*)x + i * 2;
        float4 v0 = p[0], v1 = p[1];
        __half2 h0 = __floats2half2_rn(v0.x, v0.y);
        __half2 h1 = __floats2half2_rn(v0.z, v0.w);
        __half2 h2 = __floats2half2_rn(v1.x, v1.y);
        __half2 h3 = __floats2half2_rn(v1.z, v1.w);
        uint4 u;
        u.x = *(unsigned*)&h0; u.y = *(unsigned*)&h1;
        u.z = *(unsigned*)&h2; u.w = *(unsigned*)&h3;
        *(uint4*)&g_x16[i * 8] = u;
    }
    int totalw = (F_IN * HO) >> 3;   // 12288
    if (i < totalw) {
        const float4* p = (const float4*)W + i * 2;
        float4 v0 = p[0], v1 = p[1];
        __half2 h0 = __floats2half2_rn(v0.x, v0.y);
        __half2 h1 = __floats2half2_rn(v0.z, v0.w);
        __half2 h2 = __floats2half2_rn(v1.x, v1.y);
        __half2 h3 = __floats2half2_rn(v1.z, v1.w);
        uint4 u;
        u.x = *(unsigned*)&h0; u.y = *(unsigned*)&h1;
        u.z = *(unsigned*)&h2; u.w = *(unsigned*)&h3;
        *(uint4*)&g_w16[i * 8] = u;
    }
}

// ---------------- K2: GEMM (blocks >= 1) || block-serial scan (block 0) ------
__global__ void __launch_bounds__(256) k_gemm(const float* __restrict__ att_src,
                                              const float* __restrict__ att_dst,
                                              int n) {
    __shared__ __half Ah[2][128 * 40];
    __shared__ __half Bh[2][32 * 136];
    __shared__ float Ps[128][4];
    __shared__ float Pd[128][4];
    __shared__ int wsum[8];
    __shared__ int s_carry;

    const int t = threadIdx.x;

    if (blockIdx.x == 0) {
        int lane = t & 31, w = t >> 5;
        if (t == 0) s_carry = 0;
        __syncthreads();
        for (int base = 0; base < n; base += 1024) {
            int i = base + t * 4;
            int4 v = make_int4(0, 0, 0, 0);
            if (i + 3 < n) v = *(const int4*)&g_deg[i];
            else if (i < n) {
                v.x = g_deg[i];
                if (i + 1 < n) v.y = g_deg[i + 1];
                if (i + 2 < n) v.z = g_deg[i + 2];
            }
            int s0 = v.x, s1 = s0 + v.y, s2 = s1 + v.z, s3 = s2 + v.w;
            int tot = s3;
#pragma unroll
            for (int o = 1; o < 32; o <<= 1) {
                int u = __shfl_up_sync(0xFFFFFFFFu, tot, o);
                if (lane >= o) tot += u;
            }
            if (lane == 31) wsum[w] = tot;
            __syncthreads();
            if (t < 8) {
                int ws = wsum[t];
#pragma unroll
                for (int o = 1; o < 8; o <<= 1) {
                    int u = __shfl_up_sync(0x000000FFu, ws, o);
                    if (t >= o) ws += u;
                }
                wsum[t] = ws;
            }
            __syncthreads();
            int carry = s_carry;
            int off = carry + (w > 0 ? wsum[w - 1] : 0) + (tot - s3);
            if (i < n) {
                if (i + 3 < n) {
                    int4 r = make_int4(off, off + s0, off + s1, off + s2);
                    *(int4*)&g_roff[i] = r;
                    *(int4*)&g_cursor[i] = r;
                } else {
                    g_roff[i] = off;          g_cursor[i] = off;
                    if (i + 1 < n) { g_roff[i+1] = off + s0; g_cursor[i+1] = off + s0; }
                    if (i + 2 < n) { g_roff[i+2] = off + s1; g_cursor[i+2] = off + s1; }
                }
            }
            __syncthreads();
            if (t == 255) s_carry = carry + wsum[7];
            __syncthreads();
        }
        return;
    }

    const int idx = blockIdx.x - 1;
    const int head = idx % HEADS;
    const int row0 = (idx / HEADS) * 128;
    const int lane = t & 31;
    const int wid = t >> 5;
    const int warp_m = wid & 1;
    const int warp_n = wid >> 1;

    float acc[4][4][4];
#pragma unroll
    for (int mf = 0; mf < 4; mf++)
#pragma unroll
        for (int nf = 0; nf < 4; nf++)
#pragma unroll
            for (int r = 0; r < 4; r++) acc[mf][nf][r] = 0.0f;

    auto issue = [&](int st, int kk) {
#pragma unroll
        for (int l = 0; l < 2; l++) {
            int q = t + l * 256;
            int row = q >> 2, seg = q & 3;
            bool pred = (row0 + row) < n;
            const __half* src = &g_x16[(long)(row0 + row) * F_IN + kk + seg * 8];
            cp_async16(sptr(&Ah[st][row * 40 + seg * 8]), src, pred);
        }
#pragma unroll
        for (int l = 0; l < 2; l++) {
            int q = t + l * 256;
            int kr = q >> 4, seg = q & 15;
            const __half* src = &g_w16[(long)(kk + kr) * HO + head * 128 + seg * 8];
            cp_async16(sptr(&Bh[st][kr * 136 + seg * 8]), src, true);
        }
        CP_COMMIT();
    };

    issue(0, 0);

    const int NIT = F_IN / 32;   // 8
    for (int i = 0; i < NIT; i++) {
        int st = i & 1;
        if (i + 1 < NIT) { issue((i + 1) & 1, (i + 1) * 32); CP_WAIT1(); }
        else             { CP_WAIT0(); }
        __syncthreads();

#pragma unroll
        for (int s = 0; s < 2; s++) {
            unsigned a[4][4];
#pragma unroll
            for (int mf = 0; mf < 4; mf++) {
                unsigned addr = sptr(&Ah[st][(warp_m * 64 + mf * 16 + (lane & 15)) * 40 +
                                            s * 16 + (lane >> 4) * 8]);
                LDSM4(a[mf][0], a[mf][1], a[mf][2], a[mf][3], addr);
            }
            unsigned b[2][4];
#pragma unroll
            for (int nf2 = 0; nf2 < 2; nf2++) {
                unsigned addr = sptr(&Bh[st][(s * 16 + (lane & 15)) * 136 +
                                            warp_n * 32 + nf2 * 16 + ((lane & 16) ? 8 : 0)]);
                LDSM4T(b[nf2][0], b[nf2][1], b[nf2][2], b[nf2][3], addr);
            }
#pragma unroll
            for (int mf = 0; mf < 4; mf++)
#pragma unroll
                for (int nf = 0; nf < 4; nf++) {
                    int nf2 = nf >> 1;
                    int bo = (nf & 1) * 2;
                    MMA16816(acc[mf][nf], a[mf][0], a[mf][1], a[mf][2], a[mf][3],
                             b[nf2][bo], b[nf2][bo + 1]);
                }
        }
        __syncthreads();
    }

    float avs[4][2], avd[4][2];
#pragma unroll
    for (int nf = 0; nf < 4; nf++)
#pragma unroll
        for (int j = 0; j < 2; j++) {
            int c = head * 128 + warp_n * 32 + nf * 8 + (lane & 3) * 2 + j;
            avs[nf][j] = att_src[c];
            avd[nf][j] = att_dst[c];
        }

#pragma unroll
    for (int mf = 0; mf < 4; mf++)
#pragma unroll
        for (int rh = 0; rh < 2; rh++) {
            float ps = 0.0f, pd = 0.0f;
#pragma unroll
            for (int nf = 0; nf < 4; nf++)
#pragma unroll
                for (int j = 0; j < 2; j++) {
                    float v = acc[mf][nf][rh * 2 + j];
                    ps = fmaf(v, avs[nf][j], ps);
                    pd = fmaf(v, avd[nf][j], pd);
                }
            ps += __shfl_xor_sync(0xFFFFFFFFu, ps, 1);
            ps += __shfl_xor_sync(0xFFFFFFFFu, ps, 2);
            pd += __shfl_xor_sync(0xFFFFFFFFu, pd, 1);
            pd += __shfl_xor_sync(0xFFFFFFFFu, pd, 2);
            int rloc = warp_m * 64 + mf * 16 + (lane >> 2) + rh * 8;
            if ((lane & 3) == 0) { Ps[rloc][warp_n] = ps; Pd[rloc][warp_n] = pd; }
            int grow = row0 + rloc;
            if (grow < n) {
#pragma unroll
                for (int nf = 0; nf < 4; nf++) {
                    __half2 hh = __floats2half2_rn(acc[mf][nf][rh * 2],
                                                   acc[mf][nf][rh * 2 + 1]);
                    *(__half2*)&g_h16[(long)grow * HO + head * 128 + warp_n * 32 +
                                      nf * 8 + (lane & 3) * 2] = hh;
                }
            }
        }
    __syncthreads();

    int r = t & 127;
    int grow = row0 + r;
    if (grow < n) {
        if (t < 128) {
            g_a4_src[grow * 4 + head] = Ps[r][0] + Ps[r][1] + Ps[r][2] + Ps[r][3];
        } else {
            g_a4_dst[grow * 4 + head] = Pd[r][0] + Pd[r][1] + Pd[r][2] + Pd[r][3];
        }
    }
}

// ---------------- K3: CSR fill ----------------
__global__ void k_fill(const int* __restrict__ ei, int E) {
    int i = (blockIdx.x * blockDim.x + threadIdx.x) * 4;
    if (i + 3 < E) {
        int4 s = *(const int4*)&ei[i];
        int4 d = *(const int4*)&ei[E + i];
        int p0 = atomicAdd(&g_cursor[d.x], 1); g_csr[p0] = s.x;
        int p1 = atomicAdd(&g_cursor[d.y], 1); g_csr[p1] = s.y;
        int p2 = atomicAdd(&g_cursor[d.z], 1); g_csr[p2] = s.z;
        int p3 = atomicAdd(&g_cursor[d.w], 1); g_csr[p3] = s.w;
    } else {
        for (int k = 0; k < 4 && i + k < E; k++) {
            int pos = atomicAdd(&g_cursor[ei[E + i + k]], 1);
            g_csr[pos] = ei[i + k];
        }
    }
}

// ---------------- K4: fused softmax + aggregate + relu + FC-project ----------
// one warp per dst node; two-phase chunked; 2-edge pipelined gather;
// launch_bounds(256,5) to lift occupancy (~51 regs target).
__global__ void __launch_bounds__(256, 5) k_agg(const int* __restrict__ batch,
                                                const float* __restrict__ bias,
                                                const float* __restrict__ fc_w,
                                                int n) {
    __shared__ float4 buf[8][32];

    int d = (blockIdx.x * blockDim.x + threadIdx.x) >> 5;
    int lane = threadIdx.x & 31;
    int wid = (threadIdx.x >> 5);
    if (d >= n) return;

    float ad = (lane < 3) ? g_a4_dst[d * 4 + lane] : 0.0f;
    float adst0 = __shfl_sync(0xFFFFFFFFu, ad, 0);
    float adst1 = __shfl_sync(0xFFFFFFFFu, ad, 1);
    float adst2 = __shfl_sync(0xFFFFFFFFu, ad, 2);

    float exl = 0.0f;
    if (lane < 3) {
        float v = g_a4_src[d * 4 + lane] + ad;
        v = v > 0.0f ? v : SLOPE * v;
        exl = __expf(v);
    }
    float e0 = __shfl_sync(0xFFFFFFFFu, exl, 0);
    float e1 = __shfl_sync(0xFFFFFFFFu, exl, 1);
    float e2 = __shfl_sync(0xFFFFFFFFu, exl, 2);

    float acc[3][4];
    {
        const __half* hp = &g_h16[(long)d * HO + lane * 4];
        float ee[3] = {e0, e1, e2};
#pragma unroll
        for (int h = 0; h < 3; h++) {
            uint2 u = *(const uint2*)&hp[h * OUT_C];
            float2 f01 = __half22float2(*(__half2*)&u.x);
            float2 f23 = __half22float2(*(__half2*)&u.y);
            acc[h][0] = ee[h] * f01.x;
            acc[h][1] = ee[h] * f01.y;
            acc[h][2] = ee[h] * f23.x;
            acc[h][3] = ee[h] * f23.y;
        }
    }

    int start = g_roff[d];
    int cnt = g_deg[d];
    float dl0 = 0.0f, dl1 = 0.0f, dl2 = 0.0f;

    for (int c0 = 0; c0 < cnt; c0 += 32) {
        int m = min(32, cnt - c0);
        // phase 1: one edge per lane
        int s = 0;
        float p0 = 0.0f, p1 = 0.0f, p2 = 0.0f;
        if (lane < m) {
            s = g_csr[start + c0 + lane];
            float4 a4 = *(const float4*)&g_a4_src[s * 4];
            float v0 = a4.x + adst0; v0 = v0 > 0.0f ? v0 : SLOPE * v0;
            float v1 = a4.y + adst1; v1 = v1 > 0.0f ? v1 : SLOPE * v1;
            float v2 = a4.z + adst2; v2 = v2 > 0.0f ? v2 : SLOPE * v2;
            p0 = __expf(v0); p1 = __expf(v1); p2 = __expf(v2);
            dl0 += p0; dl1 += p1; dl2 += p2;
        }
        buf[wid][lane] = make_float4(__int_as_float(s), p0, p1, p2);
        __syncwarp();

        // phase 2: 2-edge software pipeline (6 gathers in flight + next stage)
        int j = 0;
        float4 eA, eB;
        uint2 uA0, uA1, uA2, uB0, uB1, uB2;
        if (m >= 2) {
            eA = buf[wid][0];
            eB = buf[wid][1];
            const __half* pa = &g_h16[(long)__float_as_int(eA.x) * HO + lane * 4];
            const __half* pb = &g_h16[(long)__float_as_int(eB.x) * HO + lane * 4];
            uA0 = *(const uint2*)&pa[0];
            uA1 = *(const uint2*)&pa[OUT_C];
            uA2 = *(const uint2*)&pa[2 * OUT_C];
            uB0 = *(const uint2*)&pb[0];
            uB1 = *(const uint2*)&pb[OUT_C];
            uB2 = *(const uint2*)&pb[2 * OUT_C];
        }
        for (; j + 2 <= m; ) {
            float4 cA = eA, cB = eB;
            uint2 v0 = uA0, v1 = uA1, v2 = uA2;
            uint2 w0 = uB0, w1 = uB1, w2 = uB2;
            j += 2;
            if (j + 2 <= m) {   // prefetch next pair
                eA = buf[wid][j];
                eB = buf[wid][j + 1];
                const __half* pa = &g_h16[(long)__float_as_int(eA.x) * HO + lane * 4];
                const __half* pb = &g_h16[(long)__float_as_int(eB.x) * HO + lane * 4];
                uA0 = *(const uint2*)&pa[0];
                uA1 = *(const uint2*)&pa[OUT_C];
                uA2 = *(const uint2*)&pa[2 * OUT_C];
                uB0 = *(const uint2*)&pb[0];
                uB1 = *(const uint2*)&pb[OUT_C];
                uB2 = *(const uint2*)&pb[2 * OUT_C];
            }
#define ACCUM(u, w, h) { \
                float2 fa = __half22float2(*(__half2*)&(u).x); \
                float2 fb = __half22float2(*(__half2*)&(u).y); \
                acc[h][0] = fmaf((w), fa.x, acc[h][0]); \
                acc[h][1] = fmaf((w), fa.y, acc[h][1]); \
                acc[h][2] = fmaf((w), fb.x, acc[h][2]); \
                acc[h][3] = fmaf((w), fb.y, acc[h][3]); }
            ACCUM(v0, cA.y, 0) ACCUM(v1, cA.z, 1) ACCUM(v2, cA.w, 2)
            ACCUM(w0, cB.y, 0) ACCUM(w1, cB.z, 1) ACCUM(w2, cB.w, 2)
        }
        if (j < m) {
            float4 ea = buf[wid][j];
            const __half* pa = &g_h16[(long)__float_as_int(ea.x) * HO + lane * 4];
            uint2 u0 = *(const uint2*)&pa[0];
            uint2 u1 = *(const uint2*)&pa[OUT_C];
            uint2 u2 = *(const uint2*)&pa[2 * OUT_C];
            ACCUM(u0, ea.y, 0) ACCUM(u1, ea.z, 1) ACCUM(u2, ea.w, 2)
        }
#undef ACCUM
        __syncwarp();
    }

#pragma unroll
    for (int o = 16; o > 0; o >>= 1) {
        dl0 += __shfl_xor_sync(0xFFFFFFFFu, dl0, o);
        dl1 += __shfl_xor_sync(0xFFFFFFFFu, dl1, o);
        dl2 += __shfl_xor_sync(0xFFFFFFFFu, dl2, o);
    }
    float den[3] = {dl0 + e0, dl1 + e1, dl2 + e2};

    float c0s = 0.0f, c1s = 0.0f;
#pragma unroll
    for (int h = 0; h < 3; h++) {
        float inv = 1.0f / (den[h] + 1e-16f);
        int base = h * OUT_C + lane * 4;
        float4 b = *(const float4*)&bias[base];
        float r[4];
        r[0] = fmaxf(acc[h][0] * inv + b.x, 0.0f);
        r[1] = fmaxf(acc[h][1] * inv + b.y, 0.0f);
        r[2] = fmaxf(acc[h][2] * inv + b.z, 0.0f);
        r[3] = fmaxf(acc[h][3] * inv + b.w, 0.0f);
#pragma unroll
        for (int k = 0; k < 4; k++) {
            float2 w = *(const float2*)&fc_w[(base + k) * NC];
            c0s = fmaf(r[k], w.x, c0s);
            c1s = fmaf(r[k], w.y, c1s);
        }
    }
#pragma unroll
    for (int o = 16; o > 0; o >>= 1) {
        c0s += __shfl_xor_sync(0xFFFFFFFFu, c0s, o);
        c1s += __shfl_xor_sync(0xFFFFFFFFu, c1s, o);
    }
    if (lane == 0) {
        int g = batch[d];
        atomicAdd(&g_out2[g * NC + 0], c0s);
        atomicAdd(&g_out2[g * NC + 1], c1s);
        atomicAdd(&g_cnt[g], 1.0f);
        g_deg[d] = 0;   // restore invariant for next call's histogram
    }
}

// ---------------- K5: final mean + bias (+ scratch reset) --------------------
__global__ void k_final(const float* __restrict__ fc_b,
                        float* __restrict__ out) {
    int t = threadIdx.x;   // 128 threads
    float val = 0.0f;
    int g = t >> 1, c = t & 1;
    if (t < NG * NC) {
        float cnt = fmaxf(g_cnt[g], 1.0f);
        val = g_out2[t] / cnt + fc_b[c];
    }
    __syncthreads();
    if (t < NG * NC) {
        out[t] = val;
        g_out2[t] = 0.0f;
    }
    if (t < NG) g_cnt[t] = 0.0f;
}

// ---------------- launch ----------------
extern "C" void kernel_launch(void* const* d_in, const int* in_sizes, int n_in,
                              void* d_out, int out_size) {
    const float* x       = (const float*)d_in[0];
    const int*   ei      = (const int*)  d_in[1];
    const int*   batch   = (const int*)  d_in[2];
    const float* W       = (const float*)d_in[3];
    const float* att_src = (const float*)d_in[4];
    const float* att_dst = (const float*)d_in[5];
    const float* bias    = (const float*)d_in[6];
    const float* fc_w    = (const float*)d_in[7];
    const float* fc_b    = (const float*)d_in[8];
    float* out = (float*)d_out;

    const int n = in_sizes[0] / F_IN;       // 50000
    const int E = in_sizes[1] / 2;          // 800000

    int histB = (E / 4 + 255) / 256;        // 782
    int cvtB  = ((n * F_IN) / 8 + 255) / 256;  // 6250
    k_pre<<<histB + cvtB, 256>>>(x, W, ei, E, n, histB);

    int mt = (n + 127) / 128;               // 391
    k_gemm<<<1 + HEADS * mt, 256>>>(att_src, att_dst, n);

    k_fill<<<(E / 4 + 255) / 256, 256>>>(ei, E);
    k_agg<<<(n * 32 + 255) / 256, 256>>>(batch, bias, fc_w, n);
    k_final<<<1, 128>>>(fc_b, out);
}

// round 14
// speedup vs baseline: 2.0735x; 1.0372x over previous
#include <cuda_runtime.h>
#include <cuda_fp16.h>
#include <math.h>

#define N_NODES  50000
#define F_IN     256
#define HEADS    3
#define OUT_C    128
#define HO       384      // HEADS*OUT_C
#define NG       64
#define NC       2
#define E_MAX    800000
#define SLOPE    0.2f

// ---------------- scratch (device globals; zero-initialized at load) ---------
__device__ __half g_x16[N_NODES * F_IN];     // fp16 x     (25.6 MB)
__device__ __half g_w16[F_IN * HO];          // fp16 W
__device__ __half g_h16[N_NODES * HO];       // fp16 x@W   (38.4 MB)
__device__ float g_a4_src[N_NODES * 4];      // padded [node][4] logits
__device__ float g_a4_dst[N_NODES * 4];
__device__ int   g_deg[N_NODES];             // zeroed by k_agg each call
__device__ int   g_roff[N_NODES + 1];
__device__ int   g_cursor[N_NODES];
__device__ int   g_csr[E_MAX];
__device__ float g_out2[NG * NC];            // zeroed by k_final each call
__device__ float g_cnt[NG];                  // zeroed by k_final each call

// ---------------- helpers ----------------
__device__ __forceinline__ unsigned sptr(const void* p) {
    return (unsigned)__cvta_generic_to_shared(p);
}

__device__ __forceinline__ void cp_async16(unsigned dst, const void* src, bool pred) {
    int sz = pred ? 16 : 0;
    asm volatile("cp.async.cg.shared.global [%0], [%1], 16, %2;"
                 :: "r"(dst), "l"(src), "r"(sz));
}
#define CP_COMMIT() asm volatile("cp.async.commit_group;")
#define CP_WAIT1()  asm volatile("cp.async.wait_group 1;")
#define CP_WAIT0()  asm volatile("cp.async.wait_group 0;")

#define LDSM4(r0, r1, r2, r3, addr) \
    asm volatile("ldmatrix.sync.aligned.m8n8.x4.shared.b16 {%0,%1,%2,%3},[%4];" \
                 : "=r"(r0), "=r"(r1), "=r"(r2), "=r"(r3) : "r"(addr))

#define LDSM4T(r0, r1, r2, r3, addr) \
    asm volatile("ldmatrix.sync.aligned.m8n8.x4.trans.shared.b16 {%0,%1,%2,%3},[%4];" \
                 : "=r"(r0), "=r"(r1), "=r"(r2), "=r"(r3) : "r"(addr))

#define MMA16816(c, a0, a1, a2, a3, b0, b1) \
    asm volatile("mma.sync.aligned.m16n8k16.row.col.f32.f16.f16.f32 " \
                 "{%0,%1,%2,%3},{%4,%5,%6,%7},{%8,%9},{%0,%1,%2,%3};" \
                 : "+f"((c)[0]), "+f"((c)[1]), "+f"((c)[2]), "+f"((c)[3]) \
                 : "r"(a0), "r"(a1), "r"(a2), "r"(a3), "r"(b0), "r"(b1))

// ---------------- K1: hist (blocks [0,histB)) || cvt (rest) ------------------
__global__ void __launch_bounds__(256) k_pre(const float* __restrict__ x,
                                             const float* __restrict__ W,
                                             const int* __restrict__ ei,
                                             int E, int n, int histB) {
    if ((int)blockIdx.x < histB) {
        int i = (blockIdx.x * blockDim.x + threadIdx.x) * 4;
        if (i + 3 < E) {
            int4 d = *(const int4*)&ei[E + i];
            atomicAdd(&g_deg[d.x], 1);
            atomicAdd(&g_deg[d.y], 1);
            atomicAdd(&g_deg[d.z], 1);
            atomicAdd(&g_deg[d.w], 1);
        } else {
            for (int k = 0; k < 4 && i + k < E; k++)
                atomicAdd(&g_deg[ei[E + i + k]], 1);
        }
        return;
    }
    int i = (blockIdx.x - histB) * blockDim.x + threadIdx.x;
    int totalx = (n * F_IN) >> 3;
    if (i < totalx) {
        const float4* p = (const float4*)x + i * 2;
        float4 v0 = p[0], v1 = p[1];
        __half2 h0 = __floats2half2_rn(v0.x, v0.y);
        __half2 h1 = __floats2half2_rn(v0.z, v0.w);
        __half2 h2 = __floats2half2_rn(v1.x, v1.y);
        __half2 h3 = __floats2half2_rn(v1.z, v1.w);
        uint4 u;
        u.x = *(unsigned*)&h0; u.y = *(unsigned*)&h1;
        u.z = *(unsigned*)&h2; u.w = *(unsigned*)&h3;
        *(uint4*)&g_x16[i * 8] = u;
    }
    int totalw = (F_IN * HO) >> 3;   // 12288
    if (i < totalw) {
        const float4* p = (const float4*)W + i * 2;
        float4 v0 = p[0], v1 = p[1];
        __half2 h0 = __floats2half2_rn(v0.x, v0.y);
        __half2 h1 = __floats2half2_rn(v0.z, v0.w);
        __half2 h2 = __floats2half2_rn(v1.x, v1.y);
        __half2 h3 = __floats2half2_rn(v1.z, v1.w);
        uint4 u;
        u.x = *(unsigned*)&h0; u.y = *(unsigned*)&h1;
        u.z = *(unsigned*)&h2; u.w = *(unsigned*)&h3;
        *(uint4*)&g_w16[i * 8] = u;
    }
}

// ---------------- K2: GEMM (blocks >= 1) || block-serial scan (block 0) ------
__global__ void __launch_bounds__(256) k_gemm(const float* __restrict__ att_src,
                                              const float* __restrict__ att_dst,
                                              int n) {
    __shared__ __half Ah[2][128 * 40];
    __shared__ __half Bh[2][32 * 136];
    __shared__ float Ps[128][4];
    __shared__ float Pd[128][4];
    __shared__ int wsum[8];
    __shared__ int s_carry;

    const int t = threadIdx.x;

    if (blockIdx.x == 0) {
        int lane = t & 31, w = t >> 5;
        if (t == 0) s_carry = 0;
        __syncthreads();
        for (int base = 0; base < n; base += 1024) {
            int i = base + t * 4;
            int4 v = make_int4(0, 0, 0, 0);
            if (i + 3 < n) v = *(const int4*)&g_deg[i];
            else if (i < n) {
                v.x = g_deg[i];
                if (i + 1 < n) v.y = g_deg[i + 1];
                if (i + 2 < n) v.z = g_deg[i + 2];
            }
            int s0 = v.x, s1 = s0 + v.y, s2 = s1 + v.z, s3 = s2 + v.w;
            int tot = s3;
#pragma unroll
            for (int o = 1; o < 32; o <<= 1) {
                int u = __shfl_up_sync(0xFFFFFFFFu, tot, o);
                if (lane >= o) tot += u;
            }
            if (lane == 31) wsum[w] = tot;
            __syncthreads();
            if (t < 8) {
                int ws = wsum[t];
#pragma unroll
                for (int o = 1; o < 8; o <<= 1) {
                    int u = __shfl_up_sync(0x000000FFu, ws, o);
                    if (t >= o) ws += u;
                }
                wsum[t] = ws;
            }
            __syncthreads();
            int carry = s_carry;
            int off = carry + (w > 0 ? wsum[w - 1] : 0) + (tot - s3);
            if (i < n) {
                if (i + 3 < n) {
                    int4 r = make_int4(off, off + s0, off + s1, off + s2);
                    *(int4*)&g_roff[i] = r;
                    *(int4*)&g_cursor[i] = r;
                } else {
                    g_roff[i] = off;          g_cursor[i] = off;
                    if (i + 1 < n) { g_roff[i+1] = off + s0; g_cursor[i+1] = off + s0; }
                    if (i + 2 < n) { g_roff[i+2] = off + s1; g_cursor[i+2] = off + s1; }
                }
            }
            __syncthreads();
            if (t == 255) s_carry = carry + wsum[7];
            __syncthreads();
        }
        return;
    }

    const int idx = blockIdx.x - 1;
    const int head = idx % HEADS;
    const int row0 = (idx / HEADS) * 128;
    const int lane = t & 31;
    const int wid = t >> 5;
    const int warp_m = wid & 1;
    const int warp_n = wid >> 1;

    float acc[4][4][4];
#pragma unroll
    for (int mf = 0; mf < 4; mf++)
#pragma unroll
        for (int nf = 0; nf < 4; nf++)
#pragma unroll
            for (int r = 0; r < 4; r++) acc[mf][nf][r] = 0.0f;

    auto issue = [&](int st, int kk) {
#pragma unroll
        for (int l = 0; l < 2; l++) {
            int q = t + l * 256;
            int row = q >> 2, seg = q & 3;
            bool pred = (row0 + row) < n;
            const __half* src = &g_x16[(long)(row0 + row) * F_IN + kk + seg * 8];
            cp_async16(sptr(&Ah[st][row * 40 + seg * 8]), src, pred);
        }
#pragma unroll
        for (int l = 0; l < 2; l++) {
            int q = t + l * 256;
            int kr = q >> 4, seg = q & 15;
            const __half* src = &g_w16[(long)(kk + kr) * HO + head * 128 + seg * 8];
            cp_async16(sptr(&Bh[st][kr * 136 + seg * 8]), src, true);
        }
        CP_COMMIT();
    };

    issue(0, 0);

    const int NIT = F_IN / 32;   // 8
    for (int i = 0; i < NIT; i++) {
        int st = i & 1;
        if (i + 1 < NIT) { issue((i + 1) & 1, (i + 1) * 32); CP_WAIT1(); }
        else             { CP_WAIT0(); }
        __syncthreads();

#pragma unroll
        for (int s = 0; s < 2; s++) {
            unsigned a[4][4];
#pragma unroll
            for (int mf = 0; mf < 4; mf++) {
                unsigned addr = sptr(&Ah[st][(warp_m * 64 + mf * 16 + (lane & 15)) * 40 +
                                            s * 16 + (lane >> 4) * 8]);
                LDSM4(a[mf][0], a[mf][1], a[mf][2], a[mf][3], addr);
            }
            unsigned b[2][4];
#pragma unroll
            for (int nf2 = 0; nf2 < 2; nf2++) {
                unsigned addr = sptr(&Bh[st][(s * 16 + (lane & 15)) * 136 +
                                            warp_n * 32 + nf2 * 16 + ((lane & 16) ? 8 : 0)]);
                LDSM4T(b[nf2][0], b[nf2][1], b[nf2][2], b[nf2][3], addr);
            }
#pragma unroll
            for (int mf = 0; mf < 4; mf++)
#pragma unroll
                for (int nf = 0; nf < 4; nf++) {
                    int nf2 = nf >> 1;
                    int bo = (nf & 1) * 2;
                    MMA16816(acc[mf][nf], a[mf][0], a[mf][1], a[mf][2], a[mf][3],
                             b[nf2][bo], b[nf2][bo + 1]);
                }
        }
        __syncthreads();
    }

    float avs[4][2], avd[4][2];
#pragma unroll
    for (int nf = 0; nf < 4; nf++)
#pragma unroll
        for (int j = 0; j < 2; j++) {
            int c = head * 128 + warp_n * 32 + nf * 8 + (lane & 3) * 2 + j;
            avs[nf][j] = att_src[c];
            avd[nf][j] = att_dst[c];
        }

#pragma unroll
    for (int mf = 0; mf < 4; mf++)
#pragma unroll
        for (int rh = 0; rh < 2; rh++) {
            float ps = 0.0f, pd = 0.0f;
#pragma unroll
            for (int nf = 0; nf < 4; nf++)
#pragma unroll
                for (int j = 0; j < 2; j++) {
                    float v = acc[mf][nf][rh * 2 + j];
                    ps = fmaf(v, avs[nf][j], ps);
                    pd = fmaf(v, avd[nf][j], pd);
                }
            ps += __shfl_xor_sync(0xFFFFFFFFu, ps, 1);
            ps += __shfl_xor_sync(0xFFFFFFFFu, ps, 2);
            pd += __shfl_xor_sync(0xFFFFFFFFu, pd, 1);
            pd += __shfl_xor_sync(0xFFFFFFFFu, pd, 2);
            int rloc = warp_m * 64 + mf * 16 + (lane >> 2) + rh * 8;
            if ((lane & 3) == 0) { Ps[rloc][warp_n] = ps; Pd[rloc][warp_n] = pd; }
            int grow = row0 + rloc;
            if (grow < n) {
#pragma unroll
                for (int nf = 0; nf < 4; nf++) {
                    __half2 hh = __floats2half2_rn(acc[mf][nf][rh * 2],
                                                   acc[mf][nf][rh * 2 + 1]);
                    *(__half2*)&g_h16[(long)grow * HO + head * 128 + warp_n * 32 +
                                      nf * 8 + (lane & 3) * 2] = hh;
                }
            }
        }
    __syncthreads();

    int r = t & 127;
    int grow = row0 + r;
    if (grow < n) {
        if (t < 128) {
            g_a4_src[grow * 4 + head] = Ps[r][0] + Ps[r][1] + Ps[r][2] + Ps[r][3];
        } else {
            g_a4_dst[grow * 4 + head] = Pd[r][0] + Pd[r][1] + Pd[r][2] + Pd[r][3];
        }
    }
}

// ---------------- K3: CSR fill ----------------
__global__ void k_fill(const int* __restrict__ ei, int E) {
    int i = (blockIdx.x * blockDim.x + threadIdx.x) * 4;
    if (i + 3 < E) {
        int4 s = *(const int4*)&ei[i];
        int4 d = *(const int4*)&ei[E + i];
        int p0 = atomicAdd(&g_cursor[d.x], 1); g_csr[p0] = s.x;
        int p1 = atomicAdd(&g_cursor[d.y], 1); g_csr[p1] = s.y;
        int p2 = atomicAdd(&g_cursor[d.z], 1); g_csr[p2] = s.z;
        int p3 = atomicAdd(&g_cursor[d.w], 1); g_csr[p3] = s.w;
    } else {
        for (int k = 0; k < 4 && i + k < E; k++) {
            int pos = atomicAdd(&g_cursor[ei[E + i + k]], 1);
            g_csr[pos] = ei[i + k];
        }
    }
}

// ---------------- K4: fused softmax + aggregate + relu + FC-project ----------
// one warp per dst node; two-phase chunked; 6-edge gather batches
// (18 outstanding LDG.64 per warp = 4.5 KB in flight).
__global__ void __launch_bounds__(256, 3) k_agg(const int* __restrict__ batch,
                                                const float* __restrict__ bias,
                                                const float* __restrict__ fc_w,
                                                int n) {
    __shared__ float4 buf[8][32];

    int d = (blockIdx.x * blockDim.x + threadIdx.x) >> 5;
    int lane = threadIdx.x & 31;
    int wid = (threadIdx.x >> 5);
    if (d >= n) return;

    float ad = (lane < 3) ? g_a4_dst[d * 4 + lane] : 0.0f;
    float adst0 = __shfl_sync(0xFFFFFFFFu, ad, 0);
    float adst1 = __shfl_sync(0xFFFFFFFFu, ad, 1);
    float adst2 = __shfl_sync(0xFFFFFFFFu, ad, 2);

    float exl = 0.0f;
    if (lane < 3) {
        float v = g_a4_src[d * 4 + lane] + ad;
        v = v > 0.0f ? v : SLOPE * v;
        exl = __expf(v);
    }
    float e0 = __shfl_sync(0xFFFFFFFFu, exl, 0);
    float e1 = __shfl_sync(0xFFFFFFFFu, exl, 1);
    float e2 = __shfl_sync(0xFFFFFFFFu, exl, 2);

    float acc[3][4];
    {
        const __half* hp = &g_h16[(long)d * HO + lane * 4];
        float ee[3] = {e0, e1, e2};
#pragma unroll
        for (int h = 0; h < 3; h++) {
            uint2 u = *(const uint2*)&hp[h * OUT_C];
            float2 f01 = __half22float2(*(__half2*)&u.x);
            float2 f23 = __half22float2(*(__half2*)&u.y);
            acc[h][0] = ee[h] * f01.x;
            acc[h][1] = ee[h] * f01.y;
            acc[h][2] = ee[h] * f23.x;
            acc[h][3] = ee[h] * f23.y;
        }
    }

    int start = g_roff[d];
    int cnt = g_deg[d];
    float dl0 = 0.0f, dl1 = 0.0f, dl2 = 0.0f;

#define ACCUM(u, w, h) { \
        float2 fa = __half22float2(*(__half2*)&(u).x); \
        float2 fb = __half22float2(*(__half2*)&(u).y); \
        acc[h][0] = fmaf((w), fa.x, acc[h][0]); \
        acc[h][1] = fmaf((w), fa.y, acc[h][1]); \
        acc[h][2] = fmaf((w), fb.x, acc[h][2]); \
        acc[h][3] = fmaf((w), fb.y, acc[h][3]); }

    for (int c0 = 0; c0 < cnt; c0 += 32) {
        int m = min(32, cnt - c0);
        // phase 1: one edge per lane
        int s = 0;
        float p0 = 0.0f, p1 = 0.0f, p2 = 0.0f;
        if (lane < m) {
            s = g_csr[start + c0 + lane];
            float4 a4 = *(const float4*)&g_a4_src[s * 4];
            float v0 = a4.x + adst0; v0 = v0 > 0.0f ? v0 : SLOPE * v0;
            float v1 = a4.y + adst1; v1 = v1 > 0.0f ? v1 : SLOPE * v1;
            float v2 = a4.z + adst2; v2 = v2 > 0.0f ? v2 : SLOPE * v2;
            p0 = __expf(v0); p1 = __expf(v1); p2 = __expf(v2);
            dl0 += p0; dl1 += p1; dl2 += p2;
        }
        buf[wid][lane] = make_float4(__int_as_float(s), p0, p1, p2);
        __syncwarp();

        // phase 2: 6-edge gather batches (weights re-read from smem after loads)
        int j = 0;
        for (; j + 6 <= m; j += 6) {
            int sv[6];
#pragma unroll
            for (int q = 0; q < 6; q++)
                sv[q] = __float_as_int(buf[wid][j + q].x);
            uint2 u[6][3];
#pragma unroll
            for (int q = 0; q < 6; q++) {
                const __half* p = &g_h16[(long)sv[q] * HO + lane * 4];
                u[q][0] = *(const uint2*)&p[0];
                u[q][1] = *(const uint2*)&p[OUT_C];
                u[q][2] = *(const uint2*)&p[2 * OUT_C];
            }
#pragma unroll
            for (int q = 0; q < 6; q++) {
                float4 e = buf[wid][j + q];
                ACCUM(u[q][0], e.y, 0)
                ACCUM(u[q][1], e.z, 1)
                ACCUM(u[q][2], e.w, 2)
            }
        }
        for (; j < m; j++) {
            float4 ea = buf[wid][j];
            int sa = __float_as_int(ea.x);
            const __half* pa = &g_h16[(long)sa * HO + lane * 4];
            uint2 u0 = *(const uint2*)&pa[0];
            uint2 u1 = *(const uint2*)&pa[OUT_C];
            uint2 u2 = *(const uint2*)&pa[2 * OUT_C];
            ACCUM(u0, ea.y, 0) ACCUM(u1, ea.z, 1) ACCUM(u2, ea.w, 2)
        }
        __syncwarp();
    }
#undef ACCUM

#pragma unroll
    for (int o = 16; o > 0; o >>= 1) {
        dl0 += __shfl_xor_sync(0xFFFFFFFFu, dl0, o);
        dl1 += __shfl_xor_sync(0xFFFFFFFFu, dl1, o);
        dl2 += __shfl_xor_sync(0xFFFFFFFFu, dl2, o);
    }
    float den[3] = {dl0 + e0, dl1 + e1, dl2 + e2};

    float c0s = 0.0f, c1s = 0.0f;
#pragma unroll
    for (int h = 0; h < 3; h++) {
        float inv = 1.0f / (den[h] + 1e-16f);
        int base = h * OUT_C + lane * 4;
        float4 b = *(const float4*)&bias[base];
        float r[4];
        r[0] = fmaxf(acc[h][0] * inv + b.x, 0.0f);
        r[1] = fmaxf(acc[h][1] * inv + b.y, 0.0f);
        r[2] = fmaxf(acc[h][2] * inv + b.z, 0.0f);
        r[3] = fmaxf(acc[h][3] * inv + b.w, 0.0f);
#pragma unroll
        for (int k = 0; k < 4; k++) {
            float2 w = *(const float2*)&fc_w[(base + k) * NC];
            c0s = fmaf(r[k], w.x, c0s);
            c1s = fmaf(r[k], w.y, c1s);
        }
    }
#pragma unroll
    for (int o = 16; o > 0; o >>= 1) {
        c0s += __shfl_xor_sync(0xFFFFFFFFu, c0s, o);
        c1s += __shfl_xor_sync(0xFFFFFFFFu, c1s, o);
    }
    if (lane == 0) {
        int g = batch[d];
        atomicAdd(&g_out2[g * NC + 0], c0s);
        atomicAdd(&g_out2[g * NC + 1], c1s);
        atomicAdd(&g_cnt[g], 1.0f);
        g_deg[d] = 0;   // restore invariant for next call's histogram
    }
}

// ---------------- K5: final mean + bias (+ scratch reset) --------------------
__global__ void k_final(const float* __restrict__ fc_b,
                        float* __restrict__ out) {
    int t = threadIdx.x;   // 128 threads
    float val = 0.0f;
    int g = t >> 1, c = t & 1;
    if (t < NG * NC) {
        float cnt = fmaxf(g_cnt[g], 1.0f);
        val = g_out2[t] / cnt + fc_b[c];
    }
    __syncthreads();
    if (t < NG * NC) {
        out[t] = val;
        g_out2[t] = 0.0f;
    }
    if (t < NG) g_cnt[t] = 0.0f;
}

// ---------------- launch ----------------
extern "C" void kernel_launch(void* const* d_in, const int* in_sizes, int n_in,
                              void* d_out, int out_size) {
    const float* x       = (const float*)d_in[0];
    const int*   ei      = (const int*)  d_in[1];
    const int*   batch   = (const int*)  d_in[2];
    const float* W       = (const float*)d_in[3];
    const float* att_src = (const float*)d_in[4];
    const float* att_dst = (const float*)d_in[5];
    const float* bias    = (const float*)d_in[6];
    const float* fc_w    = (const float*)d_in[7];
    const float* fc_b    = (const float*)d_in[8];
    float* out = (float*)d_out;

    const int n = in_sizes[0] / F_IN;       // 50000
    const int E = in_sizes[1] / 2;          // 800000

    int histB = (E / 4 + 255) / 256;        // 782
    int cvtB  = ((n * F_IN) / 8 + 255) / 256;  // 6250
    k_pre<<<histB + cvtB, 256>>>(x, W, ei, E, n, histB);

    int mt = (n + 127) / 128;               // 391
    k_gemm<<<1 + HEADS * mt, 256>>>(att_src, att_dst, n);

    k_fill<<<(E / 4 + 255) / 256, 256>>>(ei, E);
    k_agg<<<(n * 32 + 255) / 256, 256>>>(batch, bias, fc_w, n);
    k_final<<<1, 128>>>(fc_b, out);
}

// round 15
// speedup vs baseline: 2.1893x; 1.0559x over previous
#include <cuda_runtime.h>
#include <cuda_fp16.h>
#include <math.h>

#define N_NODES  50000
#define F_IN     256
#define HEADS    3
#define OUT_C    128
#define HO       384      // HEADS*OUT_C
#define NG       64
#define NC       2
#define E_MAX    800000
#define SLOPE    0.2f

// ---------------- scratch (device globals; zero-initialized at load) ---------
__device__ __half g_x16[N_NODES * F_IN];     // fp16 x     (25.6 MB)
__device__ __half g_w16[F_IN * HO];          // fp16 W
__device__ __half g_h16[N_NODES * HO];       // fp16 x@W   (38.4 MB)
__device__ float g_a4_src[N_NODES * 4];      // padded [node][4] logits
__device__ float g_a4_dst[N_NODES * 4];
__device__ int   g_deg[N_NODES];             // zeroed by k_agg each call
__device__ int   g_roff[N_NODES + 1];
__device__ int   g_cursor[N_NODES];
__device__ int   g_csr[E_MAX];
__device__ float g_out2[NG * NC];            // zeroed by k_final each call
__device__ float g_cnt[NG];                  // zeroed by k_final each call

// ---------------- helpers ----------------
__device__ __forceinline__ unsigned sptr(const void* p) {
    return (unsigned)__cvta_generic_to_shared(p);
}

__device__ __forceinline__ void cp_async16(unsigned dst, const void* src, bool pred) {
    int sz = pred ? 16 : 0;
    asm volatile("cp.async.cg.shared.global [%0], [%1], 16, %2;"
                 :: "r"(dst), "l"(src), "r"(sz));
}
#define CP_COMMIT() asm volatile("cp.async.commit_group;")
#define CP_WAIT1()  asm volatile("cp.async.wait_group 1;")
#define CP_WAIT0()  asm volatile("cp.async.wait_group 0;")

#define LDSM4(r0, r1, r2, r3, addr) \
    asm volatile("ldmatrix.sync.aligned.m8n8.x4.shared.b16 {%0,%1,%2,%3},[%4];" \
                 : "=r"(r0), "=r"(r1), "=r"(r2), "=r"(r3) : "r"(addr))

#define LDSM4T(r0, r1, r2, r3, addr) \
    asm volatile("ldmatrix.sync.aligned.m8n8.x4.trans.shared.b16 {%0,%1,%2,%3},[%4];" \
                 : "=r"(r0), "=r"(r1), "=r"(r2), "=r"(r3) : "r"(addr))

#define MMA16816(c, a0, a1, a2, a3, b0, b1) \
    asm volatile("mma.sync.aligned.m16n8k16.row.col.f32.f16.f16.f32 " \
                 "{%0,%1,%2,%3},{%4,%5,%6,%7},{%8,%9},{%0,%1,%2,%3};" \
                 : "+f"((c)[0]), "+f"((c)[1]), "+f"((c)[2]), "+f"((c)[3]) \
                 : "r"(a0), "r"(a1), "r"(a2), "r"(a3), "r"(b0), "r"(b1))

// ---------------- K1: hist (blocks [0,histB)) || cvt (rest) ------------------
__global__ void __launch_bounds__(256) k_pre(const float* __restrict__ x,
                                             const float* __restrict__ W,
                                             const int* __restrict__ ei,
                                             int E, int n, int histB) {
    if ((int)blockIdx.x < histB) {
        int i = (blockIdx.x * blockDim.x + threadIdx.x) * 4;
        if (i + 3 < E) {
            int4 d = *(const int4*)&ei[E + i];
            atomicAdd(&g_deg[d.x], 1);
            atomicAdd(&g_deg[d.y], 1);
            atomicAdd(&g_deg[d.z], 1);
            atomicAdd(&g_deg[d.w], 1);
        } else {
            for (int k = 0; k < 4 && i + k < E; k++)
                atomicAdd(&g_deg[ei[E + i + k]], 1);
        }
        return;
    }
    int i = (blockIdx.x - histB) * blockDim.x + threadIdx.x;
    int totalx = (n * F_IN) >> 3;
    if (i < totalx) {
        const float4* p = (const float4*)x + i * 2;
        float4 v0 = p[0], v1 = p[1];
        __half2 h0 = __floats2half2_rn(v0.x, v0.y);
        __half2 h1 = __floats2half2_rn(v0.z, v0.w);
        __half2 h2 = __floats2half2_rn(v1.x, v1.y);
        __half2 h3 = __floats2half2_rn(v1.z, v1.w);
        uint4 u;
        u.x = *(unsigned*)&h0; u.y = *(unsigned*)&h1;
        u.z = *(unsigned*)&h2; u.w = *(unsigned*)&h3;
        *(uint4*)&g_x16[i * 8] = u;
    }
    int totalw = (F_IN * HO) >> 3;   // 12288
    if (i < totalw) {
        const float4* p = (const float4*)W + i * 2;
        float4 v0 = p[0], v1 = p[1];
        __half2 h0 = __floats2half2_rn(v0.x, v0.y);
        __half2 h1 = __floats2half2_rn(v0.z, v0.w);
        __half2 h2 = __floats2half2_rn(v1.x, v1.y);
        __half2 h3 = __floats2half2_rn(v1.z, v1.w);
        uint4 u;
        u.x = *(unsigned*)&h0; u.y = *(unsigned*)&h1;
        u.z = *(unsigned*)&h2; u.w = *(unsigned*)&h3;
        *(uint4*)&g_w16[i * 8] = u;
    }
}

// ---------------- K2: GEMM (blocks >= 1) || block-serial scan (block 0) ------
__global__ void __launch_bounds__(256) k_gemm(const float* __restrict__ att_src,
                                              const float* __restrict__ att_dst,
                                              int n) {
    __shared__ __half Ah[2][128 * 40];
    __shared__ __half Bh[2][32 * 136];
    __shared__ float Ps[128][4];
    __shared__ float Pd[128][4];
    __shared__ int wsum[8];
    __shared__ int s_carry;

    const int t = threadIdx.x;

    if (blockIdx.x == 0) {
        int lane = t & 31, w = t >> 5;
        if (t == 0) s_carry = 0;
        __syncthreads();
        for (int base = 0; base < n; base += 1024) {
            int i = base + t * 4;
            int4 v = make_int4(0, 0, 0, 0);
            if (i + 3 < n) v = *(const int4*)&g_deg[i];
            else if (i < n) {
                v.x = g_deg[i];
                if (i + 1 < n) v.y = g_deg[i + 1];
                if (i + 2 < n) v.z = g_deg[i + 2];
            }
            int s0 = v.x, s1 = s0 + v.y, s2 = s1 + v.z, s3 = s2 + v.w;
            int tot = s3;
#pragma unroll
            for (int o = 1; o < 32; o <<= 1) {
                int u = __shfl_up_sync(0xFFFFFFFFu, tot, o);
                if (lane >= o) tot += u;
            }
            if (lane == 31) wsum[w] = tot;
            __syncthreads();
            if (t < 8) {
                int ws = wsum[t];
#pragma unroll
                for (int o = 1; o < 8; o <<= 1) {
                    int u = __shfl_up_sync(0x000000FFu, ws, o);
                    if (t >= o) ws += u;
                }
                wsum[t] = ws;
            }
            __syncthreads();
            int carry = s_carry;
            int off = carry + (w > 0 ? wsum[w - 1] : 0) + (tot - s3);
            if (i < n) {
                if (i + 3 < n) {
                    int4 r = make_int4(off, off + s0, off + s1, off + s2);
                    *(int4*)&g_roff[i] = r;
                    *(int4*)&g_cursor[i] = r;
                } else {
                    g_roff[i] = off;          g_cursor[i] = off;
                    if (i + 1 < n) { g_roff[i+1] = off + s0; g_cursor[i+1] = off + s0; }
                    if (i + 2 < n) { g_roff[i+2] = off + s1; g_cursor[i+2] = off + s1; }
                }
            }
            __syncthreads();
            if (t == 255) s_carry = carry + wsum[7];
            __syncthreads();
        }
        return;
    }

    const int idx = blockIdx.x - 1;
    const int head = idx % HEADS;
    const int row0 = (idx / HEADS) * 128;
    const int lane = t & 31;
    const int wid = t >> 5;
    const int warp_m = wid & 1;
    const int warp_n = wid >> 1;

    float acc[4][4][4];
#pragma unroll
    for (int mf = 0; mf < 4; mf++)
#pragma unroll
        for (int nf = 0; nf < 4; nf++)
#pragma unroll
            for (int r = 0; r < 4; r++) acc[mf][nf][r] = 0.0f;

    auto issue = [&](int st, int kk) {
#pragma unroll
        for (int l = 0; l < 2; l++) {
            int q = t + l * 256;
            int row = q >> 2, seg = q & 3;
            bool pred = (row0 + row) < n;
            const __half* src = &g_x16[(long)(row0 + row) * F_IN + kk + seg * 8];
            cp_async16(sptr(&Ah[st][row * 40 + seg * 8]), src, pred);
        }
#pragma unroll
        for (int l = 0; l < 2; l++) {
            int q = t + l * 256;
            int kr = q >> 4, seg = q & 15;
            const __half* src = &g_w16[(long)(kk + kr) * HO + head * 128 + seg * 8];
            cp_async16(sptr(&Bh[st][kr * 136 + seg * 8]), src, true);
        }
        CP_COMMIT();
    };

    issue(0, 0);

    const int NIT = F_IN / 32;   // 8
    for (int i = 0; i < NIT; i++) {
        int st = i & 1;
        if (i + 1 < NIT) { issue((i + 1) & 1, (i + 1) * 32); CP_WAIT1(); }
        else             { CP_WAIT0(); }
        __syncthreads();

#pragma unroll
        for (int s = 0; s < 2; s++) {
            unsigned a[4][4];
#pragma unroll
            for (int mf = 0; mf < 4; mf++) {
                unsigned addr = sptr(&Ah[st][(warp_m * 64 + mf * 16 + (lane & 15)) * 40 +
                                            s * 16 + (lane >> 4) * 8]);
                LDSM4(a[mf][0], a[mf][1], a[mf][2], a[mf][3], addr);
            }
            unsigned b[2][4];
#pragma unroll
            for (int nf2 = 0; nf2 < 2; nf2++) {
                unsigned addr = sptr(&Bh[st][(s * 16 + (lane & 15)) * 136 +
                                            warp_n * 32 + nf2 * 16 + ((lane & 16) ? 8 : 0)]);
                LDSM4T(b[nf2][0], b[nf2][1], b[nf2][2], b[nf2][3], addr);
            }
#pragma unroll
            for (int mf = 0; mf < 4; mf++)
#pragma unroll
                for (int nf = 0; nf < 4; nf++) {
                    int nf2 = nf >> 1;
                    int bo = (nf & 1) * 2;
                    MMA16816(acc[mf][nf], a[mf][0], a[mf][1], a[mf][2], a[mf][3],
                             b[nf2][bo], b[nf2][bo + 1]);
                }
        }
        __syncthreads();
    }

    float avs[4][2], avd[4][2];
#pragma unroll
    for (int nf = 0; nf < 4; nf++)
#pragma unroll
        for (int j = 0; j < 2; j++) {
            int c = head * 128 + warp_n * 32 + nf * 8 + (lane & 3) * 2 + j;
            avs[nf][j] = att_src[c];
            avd[nf][j] = att_dst[c];
        }

#pragma unroll
    for (int mf = 0; mf < 4; mf++)
#pragma unroll
        for (int rh = 0; rh < 2; rh++) {
            float ps = 0.0f, pd = 0.0f;
#pragma unroll
            for (int nf = 0; nf < 4; nf++)
#pragma unroll
                for (int j = 0; j < 2; j++) {
                    float v = acc[mf][nf][rh * 2 + j];
                    ps = fmaf(v, avs[nf][j], ps);
                    pd = fmaf(v, avd[nf][j], pd);
                }
            ps += __shfl_xor_sync(0xFFFFFFFFu, ps, 1);
            ps += __shfl_xor_sync(0xFFFFFFFFu, ps, 2);
            pd += __shfl_xor_sync(0xFFFFFFFFu, pd, 1);
            pd += __shfl_xor_sync(0xFFFFFFFFu, pd, 2);
            int rloc = warp_m * 64 + mf * 16 + (lane >> 2) + rh * 8;
            if ((lane & 3) == 0) { Ps[rloc][warp_n] = ps; Pd[rloc][warp_n] = pd; }
            int grow = row0 + rloc;
            if (grow < n) {
#pragma unroll
                for (int nf = 0; nf < 4; nf++) {
                    __half2 hh = __floats2half2_rn(acc[mf][nf][rh * 2],
                                                   acc[mf][nf][rh * 2 + 1]);
                    *(__half2*)&g_h16[(long)grow * HO + head * 128 + warp_n * 32 +
                                      nf * 8 + (lane & 3) * 2] = hh;
                }
            }
        }
    __syncthreads();

    int r = t & 127;
    int grow = row0 + r;
    if (grow < n) {
        if (t < 128) {
            g_a4_src[grow * 4 + head] = Ps[r][0] + Ps[r][1] + Ps[r][2] + Ps[r][3];
        } else {
            g_a4_dst[grow * 4 + head] = Pd[r][0] + Pd[r][1] + Pd[r][2] + Pd[r][3];
        }
    }
}

// ---------------- K3: CSR fill ----------------
__global__ void k_fill(const int* __restrict__ ei, int E) {
    int i = (blockIdx.x * blockDim.x + threadIdx.x) * 4;
    if (i + 3 < E) {
        int4 s = *(const int4*)&ei[i];
        int4 d = *(const int4*)&ei[E + i];
        int p0 = atomicAdd(&g_cursor[d.x], 1); g_csr[p0] = s.x;
        int p1 = atomicAdd(&g_cursor[d.y], 1); g_csr[p1] = s.y;
        int p2 = atomicAdd(&g_cursor[d.z], 1); g_csr[p2] = s.z;
        int p3 = atomicAdd(&g_cursor[d.w], 1); g_csr[p3] = s.w;
    } else {
        for (int k = 0; k < 4 && i + k < E; k++) {
            int pos = atomicAdd(&g_cursor[ei[E + i + k]], 1);
            g_csr[pos] = ei[i + k];
        }
    }
}

// ---------------- K4: fused softmax + aggregate + relu + FC-project ----------
// one warp per dst node; 64-thread blocks (2 warps) for fine-grained
// scheduling; two-phase chunked with 4-edge gather batches (R9 body).
__global__ void __launch_bounds__(64) k_agg(const int* __restrict__ batch,
                                            const float* __restrict__ bias,
                                            const float* __restrict__ fc_w,
                                            int n) {
    __shared__ float4 buf[2][32];

    int d = (blockIdx.x * blockDim.x + threadIdx.x) >> 5;
    int lane = threadIdx.x & 31;
    int wid = (threadIdx.x >> 5);
    if (d >= n) return;

    float ad = (lane < 3) ? g_a4_dst[d * 4 + lane] : 0.0f;
    float adst0 = __shfl_sync(0xFFFFFFFFu, ad, 0);
    float adst1 = __shfl_sync(0xFFFFFFFFu, ad, 1);
    float adst2 = __shfl_sync(0xFFFFFFFFu, ad, 2);

    float exl = 0.0f;
    if (lane < 3) {
        float v = g_a4_src[d * 4 + lane] + ad;
        v = v > 0.0f ? v : SLOPE * v;
        exl = __expf(v);
    }
    float e0 = __shfl_sync(0xFFFFFFFFu, exl, 0);
    float e1 = __shfl_sync(0xFFFFFFFFu, exl, 1);
    float e2 = __shfl_sync(0xFFFFFFFFu, exl, 2);

    float acc[3][4];
    {
        const __half* hp = &g_h16[(long)d * HO + lane * 4];
        float ee[3] = {e0, e1, e2};
#pragma unroll
        for (int h = 0; h < 3; h++) {
            uint2 u = *(const uint2*)&hp[h * OUT_C];
            float2 f01 = __half22float2(*(__half2*)&u.x);
            float2 f23 = __half22float2(*(__half2*)&u.y);
            acc[h][0] = ee[h] * f01.x;
            acc[h][1] = ee[h] * f01.y;
            acc[h][2] = ee[h] * f23.x;
            acc[h][3] = ee[h] * f23.y;
        }
    }

    int start = g_roff[d];
    int cnt = g_deg[d];
    float dl0 = 0.0f, dl1 = 0.0f, dl2 = 0.0f;

    for (int c0 = 0; c0 < cnt; c0 += 32) {
        int m = min(32, cnt - c0);
        int s = 0;
        float p0 = 0.0f, p1 = 0.0f, p2 = 0.0f;
        if (lane < m) {
            s = g_csr[start + c0 + lane];
            float4 a4 = *(const float4*)&g_a4_src[s * 4];
            float v0 = a4.x + adst0; v0 = v0 > 0.0f ? v0 : SLOPE * v0;
            float v1 = a4.y + adst1; v1 = v1 > 0.0f ? v1 : SLOPE * v1;
            float v2 = a4.z + adst2; v2 = v2 > 0.0f ? v2 : SLOPE * v2;
            p0 = __expf(v0); p1 = __expf(v1); p2 = __expf(v2);
            dl0 += p0; dl1 += p1; dl2 += p2;
        }
        buf[wid][lane] = make_float4(__int_as_float(s), p0, p1, p2);
        __syncwarp();

        int j = 0;
        for (; j + 4 <= m; j += 4) {
            float4 e[4];
            int sv[4];
            uint2 u[4][3];
#pragma unroll
            for (int q = 0; q < 4; q++) {
                e[q] = buf[wid][j + q];
                sv[q] = __float_as_int(e[q].x);
            }
#pragma unroll
            for (int q = 0; q < 4; q++) {
                const __half* p = &g_h16[(long)sv[q] * HO + lane * 4];
                u[q][0] = *(const uint2*)&p[0];
                u[q][1] = *(const uint2*)&p[OUT_C];
                u[q][2] = *(const uint2*)&p[2 * OUT_C];
            }
#pragma unroll
            for (int q = 0; q < 4; q++) {
                float w[3] = {e[q].y, e[q].z, e[q].w};
#pragma unroll
                for (int h = 0; h < 3; h++) {
                    float2 f01 = __half22float2(*(__half2*)&u[q][h].x);
                    float2 f23 = __half22float2(*(__half2*)&u[q][h].y);
                    acc[h][0] = fmaf(w[h], f01.x, acc[h][0]);
                    acc[h][1] = fmaf(w[h], f01.y, acc[h][1]);
                    acc[h][2] = fmaf(w[h], f23.x, acc[h][2]);
                    acc[h][3] = fmaf(w[h], f23.y, acc[h][3]);
                }
            }
        }
        for (; j < m; j++) {
            float4 ea = buf[wid][j];
            int sa = __float_as_int(ea.x);
            const __half* pa = &g_h16[(long)sa * HO + lane * 4];
            float ee[3] = {ea.y, ea.z, ea.w};
#pragma unroll
            for (int h = 0; h < 3; h++) {
                uint2 u2 = *(const uint2*)&pa[h * OUT_C];
                float2 f01 = __half22float2(*(__half2*)&u2.x);
                float2 f23 = __half22float2(*(__half2*)&u2.y);
                acc[h][0] = fmaf(ee[h], f01.x, acc[h][0]);
                acc[h][1] = fmaf(ee[h], f01.y, acc[h][1]);
                acc[h][2] = fmaf(ee[h], f23.x, acc[h][2]);
                acc[h][3] = fmaf(ee[h], f23.y, acc[h][3]);
            }
        }
        __syncwarp();
    }

#pragma unroll
    for (int o = 16; o > 0; o >>= 1) {
        dl0 += __shfl_xor_sync(0xFFFFFFFFu, dl0, o);
        dl1 += __shfl_xor_sync(0xFFFFFFFFu, dl1, o);
        dl2 += __shfl_xor_sync(0xFFFFFFFFu, dl2, o);
    }
    float den[3] = {dl0 + e0, dl1 + e1, dl2 + e2};

    float c0s = 0.0f, c1s = 0.0f;
#pragma unroll
    for (int h = 0; h < 3; h++) {
        float inv = 1.0f / (den[h] + 1e-16f);
        int base = h * OUT_C + lane * 4;
        float4 b = *(const float4*)&bias[base];
        float r[4];
        r[0] = fmaxf(acc[h][0] * inv + b.x, 0.0f);
        r[1] = fmaxf(acc[h][1] * inv + b.y, 0.0f);
        r[2] = fmaxf(acc[h][2] * inv + b.z, 0.0f);
        r[3] = fmaxf(acc[h][3] * inv + b.w, 0.0f);
#pragma unroll
        for (int k = 0; k < 4; k++) {
            float2 w = *(const float2*)&fc_w[(base + k) * NC];
            c0s = fmaf(r[k], w.x, c0s);
            c1s = fmaf(r[k], w.y, c1s);
        }
    }
#pragma unroll
    for (int o = 16; o > 0; o >>= 1) {
        c0s += __shfl_xor_sync(0xFFFFFFFFu, c0s, o);
        c1s += __shfl_xor_sync(0xFFFFFFFFu, c1s, o);
    }
    if (lane == 0) {
        int g = batch[d];
        atomicAdd(&g_out2[g * NC + 0], c0s);
        atomicAdd(&g_out2[g * NC + 1], c1s);
        atomicAdd(&g_cnt[g], 1.0f);
        g_deg[d] = 0;   // restore invariant for next call's histogram
    }
}

// ---------------- K5: final mean + bias (+ scratch reset) --------------------
__global__ void k_final(const float* __restrict__ fc_b,
                        float* __restrict__ out) {
    int t = threadIdx.x;   // 128 threads
    float val = 0.0f;
    int g = t >> 1, c = t & 1;
    if (t < NG * NC) {
        float cnt = fmaxf(g_cnt[g], 1.0f);
        val = g_out2[t] / cnt + fc_b[c];
    }
    __syncthreads();
    if (t < NG * NC) {
        out[t] = val;
        g_out2[t] = 0.0f;
    }
    if (t < NG) g_cnt[t] = 0.0f;
}

// ---------------- launch ----------------
extern "C" void kernel_launch(void* const* d_in, const int* in_sizes, int n_in,
                              void* d_out, int out_size) {
    const float* x       = (const float*)d_in[0];
    const int*   ei      = (const int*)  d_in[1];
    const int*   batch   = (const int*)  d_in[2];
    const float* W       = (const float*)d_in[3];
    const float* att_src = (const float*)d_in[4];
    const float* att_dst = (const float*)d_in[5];
    const float* bias    = (const float*)d_in[6];
    const float* fc_w    = (const float*)d_in[7];
    const float* fc_b    = (const float*)d_in[8];
    float* out = (float*)d_out;

    const int n = in_sizes[0] / F_IN;       // 50000
    const int E = in_sizes[1] / 2;          // 800000

    int histB = (E / 4 + 255) / 256;        // 782
    int cvtB  = ((n * F_IN) / 8 + 255) / 256;  // 6250
    k_pre<<<histB + cvtB, 256>>>(x, W, ei, E, n, histB);

    int mt = (n + 127) / 128;               // 391
    k_gemm<<<1 + HEADS * mt, 256>>>(att_src, att_dst, n);

    k_fill<<<(E / 4 + 255) / 256, 256>>>(ei, E);
    k_agg<<<(n * 2 + 1) / 2, 64>>>(batch, bias, fc_w, n);
    k_final<<<1, 128>>>(fc_b, out);
}

// round 16
// speedup vs baseline: 2.2341x; 1.0205x over previous
#include <cuda_runtime.h>
#include <cuda_fp16.h>
#include <math.h>

#define N_NODES  50000
#define F_IN     256
#define HEADS    3
#define OUT_C    128
#define HO       384      // HEADS*OUT_C
#define NG       64
#define NC       2
#define E_MAX    800000
#define SLOPE    0.2f

// ---------------- scratch (device globals; zero-initialized at load) ---------
__device__ __half g_x16[N_NODES * F_IN];     // fp16 x     (25.6 MB)
__device__ __half g_w16[F_IN * HO];          // fp16 W
__device__ __half g_h16[N_NODES * HO];       // fp16 x@W   (38.4 MB)
__device__ float g_a4_src[N_NODES * 4];      // padded [node][4] logits
__device__ float g_a4_dst[N_NODES * 4];
__device__ int   g_deg[N_NODES];             // zeroed by k_agg each call
__device__ int   g_roff[N_NODES + 1];
__device__ int   g_cursor[N_NODES];
__device__ int   g_csr[E_MAX];
__device__ float g_out2[NG * NC];            // zeroed by k_final each call
__device__ float g_cnt[NG];                  // zeroed by k_final each call

// ---------------- helpers ----------------
__device__ __forceinline__ unsigned sptr(const void* p) {
    return (unsigned)__cvta_generic_to_shared(p);
}

__device__ __forceinline__ void cp_async16(unsigned dst, const void* src, bool pred) {
    int sz = pred ? 16 : 0;
    asm volatile("cp.async.cg.shared.global [%0], [%1], 16, %2;"
                 :: "r"(dst), "l"(src), "r"(sz));
}
#define CP_COMMIT() asm volatile("cp.async.commit_group;")
#define CP_WAIT1()  asm volatile("cp.async.wait_group 1;")
#define CP_WAIT0()  asm volatile("cp.async.wait_group 0;")

#define LDSM4(r0, r1, r2, r3, addr) \
    asm volatile("ldmatrix.sync.aligned.m8n8.x4.shared.b16 {%0,%1,%2,%3},[%4];" \
                 : "=r"(r0), "=r"(r1), "=r"(r2), "=r"(r3) : "r"(addr))

#define LDSM4T(r0, r1, r2, r3, addr) \
    asm volatile("ldmatrix.sync.aligned.m8n8.x4.trans.shared.b16 {%0,%1,%2,%3},[%4];" \
                 : "=r"(r0), "=r"(r1), "=r"(r2), "=r"(r3) : "r"(addr))

#define MMA16816(c, a0, a1, a2, a3, b0, b1) \
    asm volatile("mma.sync.aligned.m16n8k16.row.col.f32.f16.f16.f32 " \
                 "{%0,%1,%2,%3},{%4,%5,%6,%7},{%8,%9},{%0,%1,%2,%3};" \
                 : "+f"((c)[0]), "+f"((c)[1]), "+f"((c)[2]), "+f"((c)[3]) \
                 : "r"(a0), "r"(a1), "r"(a2), "r"(a3), "r"(b0), "r"(b1))

// ---------------- K1: hist (blocks [0,histB)) || cvt (rest) ------------------
__global__ void __launch_bounds__(256) k_pre(const float* __restrict__ x,
                                             const float* __restrict__ W,
                                             const int* __restrict__ ei,
                                             int E, int n, int histB) {
    if ((int)blockIdx.x < histB) {
        int i = (blockIdx.x * blockDim.x + threadIdx.x) * 4;
        if (i + 3 < E) {
            int4 d = *(const int4*)&ei[E + i];
            atomicAdd(&g_deg[d.x], 1);
            atomicAdd(&g_deg[d.y], 1);
            atomicAdd(&g_deg[d.z], 1);
            atomicAdd(&g_deg[d.w], 1);
        } else {
            for (int k = 0; k < 4 && i + k < E; k++)
                atomicAdd(&g_deg[ei[E + i + k]], 1);
        }
        return;
    }
    int i = (blockIdx.x - histB) * blockDim.x + threadIdx.x;
    int totalx = (n * F_IN) >> 3;
    if (i < totalx) {
        const float4* p = (const float4*)x + i * 2;
        float4 v0 = p[0], v1 = p[1];
        __half2 h0 = __floats2half2_rn(v0.x, v0.y);
        __half2 h1 = __floats2half2_rn(v0.z, v0.w);
        __half2 h2 = __floats2half2_rn(v1.x, v1.y);
        __half2 h3 = __floats2half2_rn(v1.z, v1.w);
        uint4 u;
        u.x = *(unsigned*)&h0; u.y = *(unsigned*)&h1;
        u.z = *(unsigned*)&h2; u.w = *(unsigned*)&h3;
        *(uint4*)&g_x16[i * 8] = u;
    }
    int totalw = (F_IN * HO) >> 3;   // 12288
    if (i < totalw) {
        const float4* p = (const float4*)W + i * 2;
        float4 v0 = p[0], v1 = p[1];
        __half2 h0 = __floats2half2_rn(v0.x, v0.y);
        __half2 h1 = __floats2half2_rn(v0.z, v0.w);
        __half2 h2 = __floats2half2_rn(v1.x, v1.y);
        __half2 h3 = __floats2half2_rn(v1.z, v1.w);
        uint4 u;
        u.x = *(unsigned*)&h0; u.y = *(unsigned*)&h1;
        u.z = *(unsigned*)&h2; u.w = *(unsigned*)&h3;
        *(uint4*)&g_w16[i * 8] = u;
    }
}

// ---------------- K2: GEMM (blocks >= 1) || block-serial scan (block 0) ------
__global__ void __launch_bounds__(256) k_gemm(const float* __restrict__ att_src,
                                              const float* __restrict__ att_dst,
                                              int n) {
    __shared__ __half Ah[2][128 * 40];
    __shared__ __half Bh[2][32 * 136];
    __shared__ float Ps[128][4];
    __shared__ float Pd[128][4];
    __shared__ int wsum[8];
    __shared__ int s_carry;

    const int t = threadIdx.x;

    if (blockIdx.x == 0) {
        int lane = t & 31, w = t >> 5;
        if (t == 0) s_carry = 0;
        __syncthreads();
        for (int base = 0; base < n; base += 1024) {
            int i = base + t * 4;
            int4 v = make_int4(0, 0, 0, 0);
            if (i + 3 < n) v = *(const int4*)&g_deg[i];
            else if (i < n) {
                v.x = g_deg[i];
                if (i + 1 < n) v.y = g_deg[i + 1];
                if (i + 2 < n) v.z = g_deg[i + 2];
            }
            int s0 = v.x, s1 = s0 + v.y, s2 = s1 + v.z, s3 = s2 + v.w;
            int tot = s3;
#pragma unroll
            for (int o = 1; o < 32; o <<= 1) {
                int u = __shfl_up_sync(0xFFFFFFFFu, tot, o);
                if (lane >= o) tot += u;
            }
            if (lane == 31) wsum[w] = tot;
            __syncthreads();
            if (t < 8) {
                int ws = wsum[t];
#pragma unroll
                for (int o = 1; o < 8; o <<= 1) {
                    int u = __shfl_up_sync(0x000000FFu, ws, o);
                    if (t >= o) ws += u;
                }
                wsum[t] = ws;
            }
            __syncthreads();
            int carry = s_carry;
            int off = carry + (w > 0 ? wsum[w - 1] : 0) + (tot - s3);
            if (i < n) {
                if (i + 3 < n) {
                    int4 r = make_int4(off, off + s0, off + s1, off + s2);
                    *(int4*)&g_roff[i] = r;
                    *(int4*)&g_cursor[i] = r;
                } else {
                    g_roff[i] = off;          g_cursor[i] = off;
                    if (i + 1 < n) { g_roff[i+1] = off + s0; g_cursor[i+1] = off + s0; }
                    if (i + 2 < n) { g_roff[i+2] = off + s1; g_cursor[i+2] = off + s1; }
                }
            }
            __syncthreads();
            if (t == 255) s_carry = carry + wsum[7];
            __syncthreads();
        }
        return;
    }

    const int idx = blockIdx.x - 1;
    const int head = idx % HEADS;
    const int row0 = (idx / HEADS) * 128;
    const int lane = t & 31;
    const int wid = t >> 5;
    const int warp_m = wid & 1;
    const int warp_n = wid >> 1;

    float acc[4][4][4];
#pragma unroll
    for (int mf = 0; mf < 4; mf++)
#pragma unroll
        for (int nf = 0; nf < 4; nf++)
#pragma unroll
            for (int r = 0; r < 4; r++) acc[mf][nf][r] = 0.0f;

    auto issue = [&](int st, int kk) {
#pragma unroll
        for (int l = 0; l < 2; l++) {
            int q = t + l * 256;
            int row = q >> 2, seg = q & 3;
            bool pred = (row0 + row) < n;
            const __half* src = &g_x16[(long)(row0 + row) * F_IN + kk + seg * 8];
            cp_async16(sptr(&Ah[st][row * 40 + seg * 8]), src, pred);
        }
#pragma unroll
        for (int l = 0; l < 2; l++) {
            int q = t + l * 256;
            int kr = q >> 4, seg = q & 15;
            const __half* src = &g_w16[(long)(kk + kr) * HO + head * 128 + seg * 8];
            cp_async16(sptr(&Bh[st][kr * 136 + seg * 8]), src, true);
        }
        CP_COMMIT();
    };

    issue(0, 0);

    const int NIT = F_IN / 32;   // 8
    for (int i = 0; i < NIT; i++) {
        int st = i & 1;
        if (i + 1 < NIT) { issue((i + 1) & 1, (i + 1) * 32); CP_WAIT1(); }
        else             { CP_WAIT0(); }
        __syncthreads();

#pragma unroll
        for (int s = 0; s < 2; s++) {
            unsigned a[4][4];
#pragma unroll
            for (int mf = 0; mf < 4; mf++) {
                unsigned addr = sptr(&Ah[st][(warp_m * 64 + mf * 16 + (lane & 15)) * 40 +
                                            s * 16 + (lane >> 4) * 8]);
                LDSM4(a[mf][0], a[mf][1], a[mf][2], a[mf][3], addr);
            }
            unsigned b[2][4];
#pragma unroll
            for (int nf2 = 0; nf2 < 2; nf2++) {
                unsigned addr = sptr(&Bh[st][(s * 16 + (lane & 15)) * 136 +
                                            warp_n * 32 + nf2 * 16 + ((lane & 16) ? 8 : 0)]);
                LDSM4T(b[nf2][0], b[nf2][1], b[nf2][2], b[nf2][3], addr);
            }
#pragma unroll
            for (int mf = 0; mf < 4; mf++)
#pragma unroll
                for (int nf = 0; nf < 4; nf++) {
                    int nf2 = nf >> 1;
                    int bo = (nf & 1) * 2;
                    MMA16816(acc[mf][nf], a[mf][0], a[mf][1], a[mf][2], a[mf][3],
                             b[nf2][bo], b[nf2][bo + 1]);
                }
        }
        __syncthreads();
    }

    float avs[4][2], avd[4][2];
#pragma unroll
    for (int nf = 0; nf < 4; nf++)
#pragma unroll
        for (int j = 0; j < 2; j++) {
            int c = head * 128 + warp_n * 32 + nf * 8 + (lane & 3) * 2 + j;
            avs[nf][j] = att_src[c];
            avd[nf][j] = att_dst[c];
        }

#pragma unroll
    for (int mf = 0; mf < 4; mf++)
#pragma unroll
        for (int rh = 0; rh < 2; rh++) {
            float ps = 0.0f, pd = 0.0f;
#pragma unroll
            for (int nf = 0; nf < 4; nf++)
#pragma unroll
                for (int j = 0; j < 2; j++) {
                    float v = acc[mf][nf][rh * 2 + j];
                    ps = fmaf(v, avs[nf][j], ps);
                    pd = fmaf(v, avd[nf][j], pd);
                }
            ps += __shfl_xor_sync(0xFFFFFFFFu, ps, 1);
            ps += __shfl_xor_sync(0xFFFFFFFFu, ps, 2);
            pd += __shfl_xor_sync(0xFFFFFFFFu, pd, 1);
            pd += __shfl_xor_sync(0xFFFFFFFFu, pd, 2);
            int rloc = warp_m * 64 + mf * 16 + (lane >> 2) + rh * 8;
            if ((lane & 3) == 0) { Ps[rloc][warp_n] = ps; Pd[rloc][warp_n] = pd; }
            int grow = row0 + rloc;
            if (grow < n) {
#pragma unroll
                for (int nf = 0; nf < 4; nf++) {
                    __half2 hh = __floats2half2_rn(acc[mf][nf][rh * 2],
                                                   acc[mf][nf][rh * 2 + 1]);
                    *(__half2*)&g_h16[(long)grow * HO + head * 128 + warp_n * 32 +
                                      nf * 8 + (lane & 3) * 2] = hh;
                }
            }
        }
    __syncthreads();

    int r = t & 127;
    int grow = row0 + r;
    if (grow < n) {
        if (t < 128) {
            g_a4_src[grow * 4 + head] = Ps[r][0] + Ps[r][1] + Ps[r][2] + Ps[r][3];
        } else {
            g_a4_dst[grow * 4 + head] = Pd[r][0] + Pd[r][1] + Pd[r][2] + Pd[r][3];
        }
    }
}

// ---------------- K3: CSR fill ----------------
__global__ void k_fill(const int* __restrict__ ei, int E) {
    int i = (blockIdx.x * blockDim.x + threadIdx.x) * 4;
    if (i + 3 < E) {
        int4 s = *(const int4*)&ei[i];
        int4 d = *(const int4*)&ei[E + i];
        int p0 = atomicAdd(&g_cursor[d.x], 1); g_csr[p0] = s.x;
        int p1 = atomicAdd(&g_cursor[d.y], 1); g_csr[p1] = s.y;
        int p2 = atomicAdd(&g_cursor[d.z], 1); g_csr[p2] = s.z;
        int p3 = atomicAdd(&g_cursor[d.w], 1); g_csr[p3] = s.w;
    } else {
        for (int k = 0; k < 4 && i + k < E; k++) {
            int pos = atomicAdd(&g_cursor[ei[E + i + k]], 1);
            g_csr[pos] = ei[i + k];
        }
    }
}

// ---------------- K4: fused softmax + aggregate + relu + FC-project ----------
// one warp per dst node; 64-thread blocks (2 warps) for fine-grained
// scheduling; two-phase chunked with 4-edge gather batches (R9 body).
__global__ void __launch_bounds__(64) k_agg(const int* __restrict__ batch,
                                            const float* __restrict__ bias,
                                            const float* __restrict__ fc_w,
                                            int n) {
    __shared__ float4 buf[2][32];

    int d = (blockIdx.x * blockDim.x + threadIdx.x) >> 5;
    int lane = threadIdx.x & 31;
    int wid = (threadIdx.x >> 5);
    if (d >= n) return;

    float ad = (lane < 3) ? g_a4_dst[d * 4 + lane] : 0.0f;
    float adst0 = __shfl_sync(0xFFFFFFFFu, ad, 0);
    float adst1 = __shfl_sync(0xFFFFFFFFu, ad, 1);
    float adst2 = __shfl_sync(0xFFFFFFFFu, ad, 2);

    float exl = 0.0f;
    if (lane < 3) {
        float v = g_a4_src[d * 4 + lane] + ad;
        v = v > 0.0f ? v : SLOPE * v;
        exl = __expf(v);
    }
    float e0 = __shfl_sync(0xFFFFFFFFu, exl, 0);
    float e1 = __shfl_sync(0xFFFFFFFFu, exl, 1);
    float e2 = __shfl_sync(0xFFFFFFFFu, exl, 2);

    float acc[3][4];
    {
        const __half* hp = &g_h16[(long)d * HO + lane * 4];
        float ee[3] = {e0, e1, e2};
#pragma unroll
        for (int h = 0; h < 3; h++) {
            uint2 u = *(const uint2*)&hp[h * OUT_C];
            float2 f01 = __half22float2(*(__half2*)&u.x);
            float2 f23 = __half22float2(*(__half2*)&u.y);
            acc[h][0] = ee[h] * f01.x;
            acc[h][1] = ee[h] * f01.y;
            acc[h][2] = ee[h] * f23.x;
            acc[h][3] = ee[h] * f23.y;
        }
    }

    int start = g_roff[d];
    int cnt = g_deg[d];
    float dl0 = 0.0f, dl1 = 0.0f, dl2 = 0.0f;

    for (int c0 = 0; c0 < cnt; c0 += 32) {
        int m = min(32, cnt - c0);
        int s = 0;
        float p0 = 0.0f, p1 = 0.0f, p2 = 0.0f;
        if (lane < m) {
            s = g_csr[start + c0 + lane];
            float4 a4 = *(const float4*)&g_a4_src[s * 4];
            float v0 = a4.x + adst0; v0 = v0 > 0.0f ? v0 : SLOPE * v0;
            float v1 = a4.y + adst1; v1 = v1 > 0.0f ? v1 : SLOPE * v1;
            float v2 = a4.z + adst2; v2 = v2 > 0.0f ? v2 : SLOPE * v2;
            p0 = __expf(v0); p1 = __expf(v1); p2 = __expf(v2);
            dl0 += p0; dl1 += p1; dl2 += p2;
        }
        buf[wid][lane] = make_float4(__int_as_float(s), p0, p1, p2);
        __syncwarp();

        int j = 0;
        for (; j + 4 <= m; j += 4) {
            float4 e[4];
            int sv[4];
            uint2 u[4][3];
#pragma unroll
            for (int q = 0; q < 4; q++) {
                e[q] = buf[wid][j + q];
                sv[q] = __float_as_int(e[q].x);
            }
#pragma unroll
            for (int q = 0; q < 4; q++) {
                const __half* p = &g_h16[(long)sv[q] * HO + lane * 4];
                u[q][0] = *(const uint2*)&p[0];
                u[q][1] = *(const uint2*)&p[OUT_C];
                u[q][2] = *(const uint2*)&p[2 * OUT_C];
            }
#pragma unroll
            for (int q = 0; q < 4; q++) {
                float w[3] = {e[q].y, e[q].z, e[q].w};
#pragma unroll
                for (int h = 0; h < 3; h++) {
                    float2 f01 = __half22float2(*(__half2*)&u[q][h].x);
                    float2 f23 = __half22float2(*(__half2*)&u[q][h].y);
                    acc[h][0] = fmaf(w[h], f01.x, acc[h][0]);
                    acc[h][1] = fmaf(w[h], f01.y, acc[h][1]);
                    acc[h][2] = fmaf(w[h], f23.x, acc[h][2]);
                    acc[h][3] = fmaf(w[h], f23.y, acc[h][3]);
                }
            }
        }
        for (; j < m; j++) {
            float4 ea = buf[wid][j];
            int sa = __float_as_int(ea.x);
            const __half* pa = &g_h16[(long)sa * HO + lane * 4];
            float ee[3] = {ea.y, ea.z, ea.w};
#pragma unroll
            for (int h = 0; h < 3; h++) {
                uint2 u2 = *(const uint2*)&pa[h * OUT_C];
                float2 f01 = __half22float2(*(__half2*)&u2.x);
                float2 f23 = __half22float2(*(__half2*)&u2.y);
                acc[h][0] = fmaf(ee[h], f01.x, acc[h][0]);
                acc[h][1] = fmaf(ee[h], f01.y, acc[h][1]);
                acc[h][2] = fmaf(ee[h], f23.x, acc[h][2]);
                acc[h][3] = fmaf(ee[h], f23.y, acc[h][3]);
            }
        }
        __syncwarp();
    }

#pragma unroll
    for (int o = 16; o > 0; o >>= 1) {
        dl0 += __shfl_xor_sync(0xFFFFFFFFu, dl0, o);
        dl1 += __shfl_xor_sync(0xFFFFFFFFu, dl1, o);
        dl2 += __shfl_xor_sync(0xFFFFFFFFu, dl2, o);
    }
    float den[3] = {dl0 + e0, dl1 + e1, dl2 + e2};

    float c0s = 0.0f, c1s = 0.0f;
#pragma unroll
    for (int h = 0; h < 3; h++) {
        float inv = 1.0f / (den[h] + 1e-16f);
        int base = h * OUT_C + lane * 4;
        float4 b = *(const float4*)&bias[base];
        float r[4];
        r[0] = fmaxf(acc[h][0] * inv + b.x, 0.0f);
        r[1] = fmaxf(acc[h][1] * inv + b.y, 0.0f);
        r[2] = fmaxf(acc[h][2] * inv + b.z, 0.0f);
        r[3] = fmaxf(acc[h][3] * inv + b.w, 0.0f);
#pragma unroll
        for (int k = 0; k < 4; k++) {
            float2 w = *(const float2*)&fc_w[(base + k) * NC];
            c0s = fmaf(r[k], w.x, c0s);
            c1s = fmaf(r[k], w.y, c1s);
        }
    }
#pragma unroll
    for (int o = 16; o > 0; o >>= 1) {
        c0s += __shfl_xor_sync(0xFFFFFFFFu, c0s, o);
        c1s += __shfl_xor_sync(0xFFFFFFFFu, c1s, o);
    }
    if (lane == 0) {
        int g = batch[d];
        atomicAdd(&g_out2[g * NC + 0], c0s);
        atomicAdd(&g_out2[g * NC + 1], c1s);
        atomicAdd(&g_cnt[g], 1.0f);
        g_deg[d] = 0;   // restore invariant for next call's histogram
    }
}

// ---------------- K5: final mean + bias (+ scratch reset) --------------------
__global__ void k_final(const float* __restrict__ fc_b,
                        float* __restrict__ out) {
    int t = threadIdx.x;   // 128 threads
    float val = 0.0f;
    int g = t >> 1, c = t & 1;
    if (t < NG * NC) {
        float cnt = fmaxf(g_cnt[g], 1.0f);
        val = g_out2[t] / cnt + fc_b[c];
    }
    __syncthreads();
    if (t < NG * NC) {
        out[t] = val;
        g_out2[t] = 0.0f;
    }
    if (t < NG) g_cnt[t] = 0.0f;
}

// ---------------- launch ----------------
extern "C" void kernel_launch(void* const* d_in, const int* in_sizes, int n_in,
                              void* d_out, int out_size) {
    const float* x       = (const float*)d_in[0];
    const int*   ei      = (const int*)  d_in[1];
    const int*   batch   = (const int*)  d_in[2];
    const float* W       = (const float*)d_in[3];
    const float* att_src = (const float*)d_in[4];
    const float* att_dst = (const float*)d_in[5];
    const float* bias    = (const float*)d_in[6];
    const float* fc_w    = (const float*)d_in[7];
    const float* fc_b    = (const float*)d_in[8];
    float* out = (float*)d_out;

    const int n = in_sizes[0] / F_IN;       // 50000
    const int E = in_sizes[1] / 2;          // 800000

    int histB = (E / 4 + 255) / 256;        // 782
    int cvtB  = ((n * F_IN) / 8 + 255) / 256;  // 6250
    k_pre<<<histB + cvtB, 256>>>(x, W, ei, E, n, histB);

    int mt = (n + 127) / 128;               // 391
    k_gemm<<<1 + HEADS * mt, 256>>>(att_src, att_dst, n);

    k_fill<<<(E / 4 + 255) / 256, 256>>>(ei, E);
    k_agg<<<(n * 2 + 1) / 2, 64>>>(batch, bias, fc_w, n);
    k_final<<<1, 128>>>(fc_b, out);
}